// round 2
// baseline (speedup 1.0000x reference)
#include <cuda_runtime.h>

// ---------------- static config ----------------
#define PNX 256
#define PNS 128
#define PI_F 3.14159265358979323846f

// sigma_mm = TIME_RES*0.3/2/2.355 = 19.108280254777070
#define SIGMA_MM   19.108280254777070f
#define INV_SIGMA  (1.0f/19.108280254777070f)
// tof_sigma_pix = sigma_mm / DX = 9.554140127388535 ; C2 = (pi*tof_sigma_pix)^2
#define FILT_C2    900.9342590332031f   // (pi*9.554140127388535)^2
// total scalar: (1/(DX*DY)) * NX / (NX*NX)  = 256/(4*65536) = 1/1024
#define FILT_SCALE (1.0f/1024.0f)

// ---------------- device scratch (allowed: __device__ globals) ----------------
__device__ float  g_img[PNX * PNX];
__device__ float2 g_freq[PNX * PNX];

// ---------------- helpers ----------------
__device__ __forceinline__ float2 cmulf(float2 a, float2 b) {
    return make_float2(a.x * b.x - a.y * b.y, a.x * b.y + a.y * b.x);
}

// 256-point radix-2 Stockham FFT in shared memory.
// 128 threads (j = 0..127). Input in bufA; result ends in bufA (8 stages).
// sign = -1 forward, +1 inverse (inverse is unnormalized).
// Caller must __syncthreads() after filling bufA.
__device__ __forceinline__ void fft256(float2* bufA, float2* bufB, int j, float sign) {
    float2* x = bufA;
    float2* y = bufB;
#pragma unroll
    for (int Ns = 1; Ns < 256; Ns <<= 1) {
        float2 v0 = x[j];
        float2 v1 = x[j + 128];
        int   k   = j & (Ns - 1);
        float ang = sign * PI_F * (float)k / (float)Ns;
        float si, co;
        __sincosf(ang, &si, &co);
        float2 tv = cmulf(v1, make_float2(co, si));
        int id = ((j - k) << 1) + k;   // (j/Ns)*2Ns + k
        y[id]      = make_float2(v0.x + tv.x, v0.y + tv.y);
        y[id + Ns] = make_float2(v0.x - tv.x, v0.y - tv.y);
        __syncthreads();
        float2* t = x; x = y; y = t;
    }
}

// shifted-frequency coordinate: filter[(k+128)%256] of linspace(-127.5..127.5)/128
__device__ __forceinline__ float freq_coord(int k) {
    return (k < 128) ? (k + 0.5f) * (1.0f / 128.0f)
                     : (k - 255.5f) * (1.0f / 128.0f);
}

// exponentially scaled modified Bessel I0: i0e(x) = exp(-x) * I0(x), x >= 0
__device__ float i0e_dev(float x) {
    if (x > 20.0f) {
        // asymptotic: 1/sqrt(2*pi*x) * sum_k ((2k-1)!!)^2 / (k! (8x)^k)
        float invx = 1.0f / x;
        float term = 1.0f, sum = 1.0f;
#pragma unroll
        for (int k = 1; k <= 6; k++) {
            float tk = (float)(2 * k - 1);
            term *= tk * tk * invx / (8.0f * (float)k);
            sum  += term;
        }
        return sum * rsqrtf(2.0f * PI_F * x);
    } else {
        // 64-pt midpoint quadrature of (1/pi) * int_0^pi exp(x(cos t - 1)) dt
        float s = 0.0f;
        for (int j = 0; j < 64; j++) {
            float th = ((float)j + 0.5f) * (PI_F / 64.0f);
            s += __expf(x * (__cosf(th) - 1.0f));
        }
        return s * (1.0f / 64.0f);
    }
}

// ---------------- kernels ----------------
__global__ void k_zero() {
    int i = blockIdx.x * blockDim.x + threadIdx.x;
    g_img[i] = 0.0f;
}

__global__ void k_bp(const float* __restrict__ proj, const float* __restrict__ tof,
                     const float* __restrict__ x1l, const float* __restrict__ y1l,
                     const float* __restrict__ x1r, const float* __restrict__ y1r,
                     const float* __restrict__ x2l, const float* __restrict__ y2l,
                     const float* __restrict__ x2r, const float* __restrict__ y2r,
                     int n) {
    int e = blockIdx.x * blockDim.x + threadIdx.x;
    if (e >= n) return;

    float x1 = 0.5f * (x1l[e] + x1r[e]);
    float y1 = 0.5f * (y1l[e] + y1r[e]);
    float x2 = 0.5f * (x2l[e] + x2r[e]);
    float y2 = 0.5f * (y2l[e] + y2r[e]);
    float ddx = x2 - x1, ddy = y2 - y1;
    float L = sqrtf(ddx * ddx + ddy * ddy);

    float step     = L * (1.0f / (float)PNS);
    float inv_step = (float)PNS / L;
    float center   = 0.5f * L + 0.15f * tof[e];
    float p        = proj[e] * step;   // fold step length into weight

    // Gaussian support window: |s - center| <= 6.5 sigma  (tail < 8e-10)
    float lo = (center - 6.5f * SIGMA_MM) * inv_step - 0.5f;
    float hi = (center + 6.5f * SIGMA_MM) * inv_step - 0.5f;
    int i0 = max(0,   (int)ceilf(lo));
    int i1 = min(127, (int)floorf(hi));

    for (int i = i0; i <= i1; i++) {
        float t = ((float)i + 0.5f) * (1.0f / (float)PNS);
        float s = t * L;
        float z = (s - center) * INV_SIGMA;
        float w = __expf(-0.5f * z * z);
        float px = fmaf(t, ddx, x1);
        float py = fmaf(t, ddy, y1);
        int ix = (int)floorf(fmaf(px, 0.5f, 128.0f));   // px/DX + NX/2
        int iy = (int)floorf(fmaf(py, 0.5f, 128.0f));
        if ((unsigned)ix < 256u && (unsigned)iy < 256u)
            atomicAdd(&g_img[iy * PNX + ix], w * p);
    }
}

__global__ void k_fft_rows_fwd() {
    __shared__ float2 A[256];
    __shared__ float2 B[256];
    int row = blockIdx.x, j = threadIdx.x;
    A[j]       = make_float2(g_img[row * PNX + j],       0.0f);
    A[j + 128] = make_float2(g_img[row * PNX + j + 128], 0.0f);
    __syncthreads();
    fft256(A, B, j, -1.0f);
    g_freq[row * PNX + j]       = A[j];
    g_freq[row * PNX + j + 128] = A[j + 128];
}

// fused: column forward FFT -> TOF deblur filter (+ all scalars) -> column inverse FFT
__global__ void k_fft_cols_filter() {
    __shared__ float2 A[256];
    __shared__ float2 B[256];
    int c = blockIdx.x, j = threadIdx.x;
    A[j]       = g_freq[j * PNX + c];
    A[j + 128] = g_freq[(j + 128) * PNX + c];
    __syncthreads();
    fft256(A, B, j, -1.0f);

    float fc  = freq_coord(c);
    float fc2 = fc * fc;
#pragma unroll
    for (int kk = j; kk < 256; kk += 128) {
        float fr = freq_coord(kk);
        float w0 = fmaf(fr, fr, fc2);
        float g  = FILT_SCALE / i0e_dev(w0 * FILT_C2);
        A[kk].x *= g;
        A[kk].y *= g;
    }
    __syncthreads();
    fft256(A, B, j, +1.0f);
    g_freq[j * PNX + c]         = A[j];
    g_freq[(j + 128) * PNX + c] = A[j + 128];
}

__global__ void k_fft_rows_inv(float* __restrict__ out) {
    __shared__ float2 A[256];
    __shared__ float2 B[256];
    int row = blockIdx.x, j = threadIdx.x;
    A[j]       = g_freq[row * PNX + j];
    A[j + 128] = g_freq[row * PNX + j + 128];
    __syncthreads();
    fft256(A, B, j, +1.0f);
    out[row * PNX + j]       = A[j].x;
    out[row * PNX + j + 128] = A[j + 128].x;
}

// ---------------- launch ----------------
extern "C" void kernel_launch(void* const* d_in, const int* in_sizes, int n_in,
                              void* d_out, int out_size) {
    const float* proj = (const float*)d_in[0];
    const float* tof  = (const float*)d_in[1];
    const float* x1l  = (const float*)d_in[2];
    const float* y1l  = (const float*)d_in[3];
    const float* x1r  = (const float*)d_in[4];
    const float* y1r  = (const float*)d_in[5];
    const float* x2l  = (const float*)d_in[6];
    const float* y2l  = (const float*)d_in[7];
    const float* x2r  = (const float*)d_in[8];
    const float* y2r  = (const float*)d_in[9];
    int n = in_sizes[0];

    k_zero<<<(PNX * PNX) / 256, 256>>>();
    k_bp<<<(n + 127) / 128, 128>>>(proj, tof, x1l, y1l, x1r, y1r,
                                   x2l, y2l, x2r, y2r, n);
    k_fft_rows_fwd<<<PNX, 128>>>();
    k_fft_cols_filter<<<PNX, 128>>>();
    k_fft_rows_inv<<<PNX, 128>>>((float*)d_out);
}

// round 4
// speedup vs baseline: 1.1346x; 1.1346x over previous
#include <cuda_runtime.h>

// ---------------- static config ----------------
#define PNX 256
#define PNS 128
#define PI_F 3.14159265358979323846f

// sigma_mm = TIME_RES*0.3/2/2.355 = 19.108280254777070
#define SIGMA_MM   19.108280254777070f
#define INV_SIGMA  (1.0f/19.108280254777070f)
// (pi * tof_sigma_pix)^2, tof_sigma_pix = 9.554140127388535
#define FILT_C2    900.91346f
// (1/(DX*DY)) * NX / (NX*NX) = 1/1024
#define FILT_SCALE (1.0f/1024.0f)
#define WIN_NSIG   5.0f

// ---------------- device scratch ----------------
__device__ float  g_img[PNX * PNX];     // zero-initialized at load; re-zeroed each call
__device__ float2 g_freq[PNX * PNX];

// ---------------- helpers ----------------
// 256-pt radix-2 Stockham FFT, 128 threads, shared twiddle table W[128]:
// W[m] = (cos(pi*m/128), sin(pi*m/128)). sign = -1 fwd, +1 inv (unnormalized).
__device__ __forceinline__ void fft256(float2* bufA, float2* bufB,
                                       const float2* __restrict__ W,
                                       int j, float sign) {
    float2* x = bufA;
    float2* y = bufB;
#pragma unroll
    for (int st = 0; st < 8; st++) {
        int Ns = 1 << st;
        float2 v0 = x[j];
        float2 v1 = x[j + 128];
        int k = j & (Ns - 1);
        float2 w = W[k << (7 - st)];
        float wy = sign * w.y;           // exp(sign*i*theta)
        float2 tv = make_float2(v1.x * w.x - v1.y * wy,
                                v1.x * wy + v1.y * w.x);
        int id = ((j - k) << 1) + k;
        y[id]      = make_float2(v0.x + tv.x, v0.y + tv.y);
        y[id + Ns] = make_float2(v0.x - tv.x, v0.y - tv.y);
        __syncthreads();
        float2* t = x; x = y; y = t;
    }
}

__device__ __forceinline__ void fill_twiddles(float2* W, int j) {
    float s, c;
    sincospif((float)j * (1.0f / 128.0f), &s, &c);
    W[j] = make_float2(c, s);
}

// shifted-frequency coordinate: filter[(k+128)%256] of linspace(-127.5..127.5)/128
__device__ __forceinline__ float freq_coord(int k) {
    return (k < 128) ? (k + 0.5f) * (1.0f / 128.0f)
                     : (k - 255.5f) * (1.0f / 128.0f);
}

// i0e(x) = exp(-x)*I0(x), x in [0, ~1800]
__device__ float i0e_dev(float x) {
    if (x > 8.0f) {
        // asymptotic: 1/sqrt(2 pi x) * sum ((2k-1)!!)^2/(k! (8x)^k); err < 1e-6 at x=8
        float invx = 1.0f / x;
        float term = 1.0f, sum = 1.0f;
#pragma unroll
        for (int k = 1; k <= 6; k++) {
            float tk = (float)(2 * k - 1);
            term *= tk * tk * invx * (1.0f / (8.0f * (float)k));
            sum  += term;
        }
        return sum * rsqrtf(2.0f * PI_F * x);
    } else {
        // power series: I0(x) = sum (x^2/4)^k / (k!)^2, all-positive, 22 terms
        float q = 0.25f * x * x;
        float term = 1.0f, sum = 1.0f;
#pragma unroll
        for (int k = 1; k <= 22; k++) {
            float ik = 1.0f / (float)k;
            term *= q * ik * ik;
            sum  += term;
        }
        return sum * __expf(-x);
    }
}

// ---------------- kernels ----------------
__global__ void k_bp(const float* __restrict__ proj, const float* __restrict__ tof,
                     const float* __restrict__ x1l, const float* __restrict__ y1l,
                     const float* __restrict__ x1r, const float* __restrict__ y1r,
                     const float* __restrict__ x2l, const float* __restrict__ y2l,
                     const float* __restrict__ x2r, const float* __restrict__ y2r,
                     int n) {
    int e = blockIdx.x * blockDim.x + threadIdx.x;
    if (e >= n) return;

    float x1 = 0.5f * (x1l[e] + x1r[e]);
    float y1 = 0.5f * (y1l[e] + y1r[e]);
    float x2 = 0.5f * (x2l[e] + x2r[e]);
    float y2 = 0.5f * (y2l[e] + y2r[e]);
    float ddx = x2 - x1, ddy = y2 - y1;
    float L = sqrtf(ddx * ddx + ddy * ddy);

    float step     = L * (1.0f / (float)PNS);
    float inv_step = (float)PNS / L;
    float center   = 0.5f * L + 0.15f * tof[e];

    // Gaussian support window
    float lo = (center - WIN_NSIG * SIGMA_MM) * inv_step - 0.5f;
    float hi = (center + WIN_NSIG * SIGMA_MM) * inv_step - 0.5f;
    int i0 = max(0,   (int)ceilf(lo));
    int i1 = min(127, (int)floorf(hi));
    if (i0 > i1) return;

    // incremental Gaussian weight (smooth quantity, drift ~1e-5: harmless):
    // w_{i+1} = w_i * r_i ; r_{i+1} = r_i * c
    float dz = step * INV_SIGMA;
    float z0 = (((float)i0 + 0.5f) * step - center) * INV_SIGMA;
    float w  = proj[e] * step * __expf(-0.5f * z0 * z0);
    float r  = __expf(-dz * (z0 + 0.5f * dz));
    float c  = __expf(-dz * dz);

    // t advanced incrementally — EXACT in fp32 (all values are (2i+1)/256).
    // Pixel index math recomputed per-sample, bit-matching the R2 formulation:
    // px = fma(t,ddx,x1); gx = fma(px,0.5,128) (single rounding == px/2+128).
    float t = ((float)i0 + 0.5f) * (1.0f / (float)PNS);

#pragma unroll 4
    for (int i = i0; i <= i1; i++) {
        float px = fmaf(t, ddx, x1);
        float py = fmaf(t, ddy, y1);
        int ix = (int)floorf(fmaf(px, 0.5f, 128.0f));
        int iy = (int)floorf(fmaf(py, 0.5f, 128.0f));
        if (((unsigned)ix < 256u) && ((unsigned)iy < 256u))
            atomicAdd(&g_img[iy * PNX + ix], w);
        w *= r;  r *= c;
        t += (1.0f / (float)PNS);
    }
}

__global__ void k_fft_rows_fwd() {
    __shared__ float2 A[256];
    __shared__ float2 B[256];
    __shared__ float2 W[128];
    int row = blockIdx.x, j = threadIdx.x;
    fill_twiddles(W, j);
    A[j]       = make_float2(g_img[row * PNX + j],       0.0f);
    A[j + 128] = make_float2(g_img[row * PNX + j + 128], 0.0f);
    // re-zero accumulator for the next invocation (device globals start zeroed)
    g_img[row * PNX + j]       = 0.0f;
    g_img[row * PNX + j + 128] = 0.0f;
    __syncthreads();
    fft256(A, B, W, j, -1.0f);
    g_freq[row * PNX + j]       = A[j];
    g_freq[row * PNX + j + 128] = A[j + 128];
}

// fused: column fwd FFT -> TOF deblur filter (+scalars) -> column inv FFT
__global__ void k_fft_cols_filter() {
    __shared__ float2 A[256];
    __shared__ float2 B[256];
    __shared__ float2 W[128];
    int c = blockIdx.x, j = threadIdx.x;
    fill_twiddles(W, j);
    A[j]       = g_freq[j * PNX + c];
    A[j + 128] = g_freq[(j + 128) * PNX + c];
    __syncthreads();
    fft256(A, B, W, j, -1.0f);

    float fc  = freq_coord(c);
    float fc2 = fc * fc;
#pragma unroll
    for (int kk = j; kk < 256; kk += 128) {
        float fr = freq_coord(kk);
        float w0 = fmaf(fr, fr, fc2);
        float g  = FILT_SCALE / i0e_dev(w0 * FILT_C2);
        A[kk].x *= g;
        A[kk].y *= g;
    }
    __syncthreads();
    fft256(A, B, W, j, +1.0f);
    g_freq[j * PNX + c]         = A[j];
    g_freq[(j + 128) * PNX + c] = A[j + 128];
}

__global__ void k_fft_rows_inv(float* __restrict__ out) {
    __shared__ float2 A[256];
    __shared__ float2 B[256];
    __shared__ float2 W[128];
    int row = blockIdx.x, j = threadIdx.x;
    fill_twiddles(W, j);
    A[j]       = g_freq[row * PNX + j];
    A[j + 128] = g_freq[row * PNX + j + 128];
    __syncthreads();
    fft256(A, B, W, j, +1.0f);
    out[row * PNX + j]       = A[j].x;
    out[row * PNX + j + 128] = A[j + 128].x;
}

// ---------------- launch ----------------
extern "C" void kernel_launch(void* const* d_in, const int* in_sizes, int n_in,
                              void* d_out, int out_size) {
    const float* proj = (const float*)d_in[0];
    const float* tof  = (const float*)d_in[1];
    const float* x1l  = (const float*)d_in[2];
    const float* y1l  = (const float*)d_in[3];
    const float* x1r  = (const float*)d_in[4];
    const float* y1r  = (const float*)d_in[5];
    const float* x2l  = (const float*)d_in[6];
    const float* y2l  = (const float*)d_in[7];
    const float* x2r  = (const float*)d_in[8];
    const float* y2r  = (const float*)d_in[9];
    int n = in_sizes[0];

    k_bp<<<(n + 255) / 256, 256>>>(proj, tof, x1l, y1l, x1r, y1r,
                                   x2l, y2l, x2r, y2r, n);
    k_fft_rows_fwd<<<PNX, 128>>>();
    k_fft_cols_filter<<<PNX, 128>>>();
    k_fft_rows_inv<<<PNX, 128>>>((float*)d_out);
}

// round 5
// speedup vs baseline: 1.2457x; 1.0979x over previous
#include <cuda_runtime.h>

// ---------------- static config ----------------
#define PNX 256
#define PNS 128
#define PI_F 3.14159265358979323846f

// sigma_mm = TIME_RES*0.3/2/2.355 = 19.108280254777070
#define SIGMA_MM   19.108280254777070f
#define INV_SIGMA  (1.0f/19.108280254777070f)
// (pi * tof_sigma_pix)^2, tof_sigma_pix = 9.554140127388535
#define FILT_C2    900.91346f
// (1/(DX*DY)) * NX / (NX*NX) = 1/1024
#define FILT_SCALE (1.0f/1024.0f)
#define WIN_NSIG   4.25f

// ---------------- device scratch ----------------
__device__ float  g_img[PNX * PNX];     // zero-initialized at load; re-zeroed each call
__device__ float2 g_freq[PNX * PNX];

// ---------------- helpers ----------------
// 256-pt radix-2 Stockham FFT, 128 threads per line, shared twiddle table W[128]:
// W[m] = (cos(pi*m/128), sin(pi*m/128)). sign = -1 fwd, +1 inv (unnormalized).
// NOTE: __syncthreads() spans the whole block; all line-groups in a block run
// the same 8 stages in lockstep, so this is safe with multiple lines per block.
__device__ __forceinline__ void fft256(float2* bufA, float2* bufB,
                                       const float2* __restrict__ W,
                                       int j, float sign) {
    float2* x = bufA;
    float2* y = bufB;
#pragma unroll
    for (int st = 0; st < 8; st++) {
        int Ns = 1 << st;
        float2 v0 = x[j];
        float2 v1 = x[j + 128];
        int k = j & (Ns - 1);
        float2 w = W[k << (7 - st)];
        float wy = sign * w.y;           // exp(sign*i*theta)
        float2 tv = make_float2(v1.x * w.x - v1.y * wy,
                                v1.x * wy + v1.y * w.x);
        int id = ((j - k) << 1) + k;
        y[id]      = make_float2(v0.x + tv.x, v0.y + tv.y);
        y[id + Ns] = make_float2(v0.x - tv.x, v0.y - tv.y);
        __syncthreads();
        float2* t = x; x = y; y = t;
    }
}

__device__ __forceinline__ void fill_twiddles(float2* W, int tid) {
    if (tid < 128) {
        float s, c;
        sincospif((float)tid * (1.0f / 128.0f), &s, &c);
        W[tid] = make_float2(c, s);
    }
}

// shifted-frequency coordinate: filter[(k+128)%256] of linspace(-127.5..127.5)/128
__device__ __forceinline__ float freq_coord(int k) {
    return (k < 128) ? (k + 0.5f) * (1.0f / 128.0f)
                     : (k - 255.5f) * (1.0f / 128.0f);
}

// i0e(x) = exp(-x)*I0(x), x in [0, ~1800]
__device__ float i0e_dev(float x) {
    if (x > 8.0f) {
        float invx = 1.0f / x;
        float term = 1.0f, sum = 1.0f;
#pragma unroll
        for (int k = 1; k <= 6; k++) {
            float tk = (float)(2 * k - 1);
            term *= tk * tk * invx * (1.0f / (8.0f * (float)k));
            sum  += term;
        }
        return sum * rsqrtf(2.0f * PI_F * x);
    } else {
        float q = 0.25f * x * x;
        float term = 1.0f, sum = 1.0f;
#pragma unroll
        for (int k = 1; k <= 22; k++) {
            float ik = 1.0f / (float)k;
            term *= q * ik * ik;
            sum  += term;
        }
        return sum * __expf(-x);
    }
}

// ---------------- kernels ----------------
__global__ void k_bp(const float* __restrict__ proj, const float* __restrict__ tof,
                     const float* __restrict__ x1l, const float* __restrict__ y1l,
                     const float* __restrict__ x1r, const float* __restrict__ y1r,
                     const float* __restrict__ x2l, const float* __restrict__ y2l,
                     const float* __restrict__ x2r, const float* __restrict__ y2r,
                     int n) {
    int e = blockIdx.x * blockDim.x + threadIdx.x;
    if (e >= n) return;

    float x1 = 0.5f * (x1l[e] + x1r[e]);
    float y1 = 0.5f * (y1l[e] + y1r[e]);
    float x2 = 0.5f * (x2l[e] + x2r[e]);
    float y2 = 0.5f * (y2l[e] + y2r[e]);
    float ddx = x2 - x1, ddy = y2 - y1;
    float L = sqrtf(ddx * ddx + ddy * ddy);

    float step     = L * (1.0f / (float)PNS);
    float inv_step = (float)PNS / L;
    float center   = 0.5f * L + 0.15f * tof[e];

    // Gaussian support window
    float lo = (center - WIN_NSIG * SIGMA_MM) * inv_step - 0.5f;
    float hi = (center + WIN_NSIG * SIGMA_MM) * inv_step - 0.5f;
    int i0 = max(0,   (int)ceilf(lo));
    int i1 = min(127, (int)floorf(hi));
    if (i0 > i1) return;

    // incremental Gaussian weight: w_{i+1} = w_i * r_i ; r_{i+1} = r_i * c
    float dz = step * INV_SIGMA;
    float z0 = (((float)i0 + 0.5f) * step - center) * INV_SIGMA;
    float w  = proj[e] * step * __expf(-0.5f * z0 * z0);
    float r  = __expf(-dz * (z0 + 0.5f * dz));
    float c  = __expf(-dz * dz);

    // t advanced incrementally — EXACT in fp32 (all values are (2i+1)/256).
    // Pixel index math per-sample, bit-matching the R2/R4 formulation.
    float t = ((float)i0 + 0.5f) * (1.0f / (float)PNS);

#pragma unroll 8
    for (int i = i0; i <= i1; i++) {
        float px = fmaf(t, ddx, x1);
        float py = fmaf(t, ddy, y1);
        int ix = __float2int_rd(fmaf(px, 0.5f, 128.0f));
        int iy = __float2int_rd(fmaf(py, 0.5f, 128.0f));
        if ((unsigned)(ix | iy) < 256u)
            atomicAdd(&g_img[iy * PNX + ix], w);
        w *= r;  r *= c;
        t += (1.0f / (float)PNS);
    }
}

// 2 rows per block: 256 threads, group g = tid>>7 handles row 2*blockIdx+g
__global__ void k_fft_rows_fwd() {
    __shared__ float2 A[2][256];
    __shared__ float2 B[2][256];
    __shared__ float2 W[128];
    int g = threadIdx.x >> 7;
    int j = threadIdx.x & 127;
    int row = blockIdx.x * 2 + g;
    fill_twiddles(W, threadIdx.x);
    A[g][j]       = make_float2(g_img[row * PNX + j],       0.0f);
    A[g][j + 128] = make_float2(g_img[row * PNX + j + 128], 0.0f);
    // re-zero accumulator for the next invocation
    g_img[row * PNX + j]       = 0.0f;
    g_img[row * PNX + j + 128] = 0.0f;
    __syncthreads();
    fft256(A[g], B[g], W, j, -1.0f);
    g_freq[row * PNX + j]       = A[g][j];
    g_freq[row * PNX + j + 128] = A[g][j + 128];
}

// fused: column fwd FFT -> TOF deblur filter (+scalars) -> column inv FFT
// 2 adjacent columns per block (groups load adjacent addresses -> shared L2 sectors)
__global__ void k_fft_cols_filter() {
    __shared__ float2 A[2][256];
    __shared__ float2 B[2][256];
    __shared__ float2 W[128];
    int g = threadIdx.x >> 7;
    int j = threadIdx.x & 127;
    int c = blockIdx.x * 2 + g;
    fill_twiddles(W, threadIdx.x);
    A[g][j]       = g_freq[j * PNX + c];
    A[g][j + 128] = g_freq[(j + 128) * PNX + c];
    __syncthreads();
    fft256(A[g], B[g], W, j, -1.0f);

    float fc  = freq_coord(c);
    float fc2 = fc * fc;
#pragma unroll
    for (int kk = j; kk < 256; kk += 128) {
        float fr = freq_coord(kk);
        float w0 = fmaf(fr, fr, fc2);
        float gn = FILT_SCALE / i0e_dev(w0 * FILT_C2);
        A[g][kk].x *= gn;
        A[g][kk].y *= gn;
    }
    __syncthreads();
    fft256(A[g], B[g], W, j, +1.0f);
    g_freq[j * PNX + c]         = A[g][j];
    g_freq[(j + 128) * PNX + c] = A[g][j + 128];
}

__global__ void k_fft_rows_inv(float* __restrict__ out) {
    __shared__ float2 A[2][256];
    __shared__ float2 B[2][256];
    __shared__ float2 W[128];
    int g = threadIdx.x >> 7;
    int j = threadIdx.x & 127;
    int row = blockIdx.x * 2 + g;
    fill_twiddles(W, threadIdx.x);
    A[g][j]       = g_freq[row * PNX + j];
    A[g][j + 128] = g_freq[row * PNX + j + 128];
    __syncthreads();
    fft256(A[g], B[g], W, j, +1.0f);
    out[row * PNX + j]       = A[g][j].x;
    out[row * PNX + j + 128] = A[g][j + 128].x;
}

// ---------------- launch ----------------
extern "C" void kernel_launch(void* const* d_in, const int* in_sizes, int n_in,
                              void* d_out, int out_size) {
    const float* proj = (const float*)d_in[0];
    const float* tof  = (const float*)d_in[1];
    const float* x1l  = (const float*)d_in[2];
    const float* y1l  = (const float*)d_in[3];
    const float* x1r  = (const float*)d_in[4];
    const float* y1r  = (const float*)d_in[5];
    const float* x2l  = (const float*)d_in[6];
    const float* y2l  = (const float*)d_in[7];
    const float* x2r  = (const float*)d_in[8];
    const float* y2r  = (const float*)d_in[9];
    int n = in_sizes[0];

    k_bp<<<(n + 255) / 256, 256>>>(proj, tof, x1l, y1l, x1r, y1r,
                                   x2l, y2l, x2r, y2r, n);
    k_fft_rows_fwd<<<PNX / 2, 256>>>();
    k_fft_cols_filter<<<PNX / 2, 256>>>();
    k_fft_rows_inv<<<PNX / 2, 256>>>((float*)d_out);
}

// round 6
// speedup vs baseline: 1.3746x; 1.1035x over previous
#include <cuda_runtime.h>
#include <cstdint>

// ---------------- static config ----------------
#define PNX 256
#define PNS 128
#define PI_F 3.14159265358979323846f

// sigma_mm = TIME_RES*0.3/2/2.355 = 19.108280254777070
#define SIGMA_MM   19.108280254777070f
#define INV_SIGMA  (1.0f/19.108280254777070f)
// (pi * tof_sigma_pix)^2, tof_sigma_pix = 9.554140127388535
#define FILT_C2    900.91346f
// (1/(DX*DY)) * NX / (NX*NX) = 1/1024
#define FILT_SCALE (1.0f/1024.0f)
#define WIN_NSIG   3.5f

// ---------------- device scratch ----------------
__device__ float  g_img[PNX * PNX];     // zero-initialized at load; re-zeroed each call
__device__ float2 g_freq[PNX * PNX];

// ---------------- packed f32x2 helpers (sm_100a) ----------------
__device__ __forceinline__ uint64_t pack2(float lo, float hi) {
    uint64_t r;
    asm("mov.b64 %0, {%1, %2};" : "=l"(r) : "f"(lo), "f"(hi));
    return r;
}
__device__ __forceinline__ void unpack2(uint64_t v, float& lo, float& hi) {
    asm("mov.b64 {%0, %1}, %2;" : "=f"(lo), "=f"(hi) : "l"(v));
}
__device__ __forceinline__ uint64_t fma2(uint64_t a, uint64_t b, uint64_t c) {
    uint64_t r;
    asm("fma.rn.f32x2 %0, %1, %2, %3;" : "=l"(r) : "l"(a), "l"(b), "l"(c));
    return r;
}
__device__ __forceinline__ uint64_t add2(uint64_t a, uint64_t b) {
    uint64_t r;
    asm("add.rn.f32x2 %0, %1, %2;" : "=l"(r) : "l"(a), "l"(b));
    return r;
}

// ---------------- FFT helpers ----------------
// 256-pt radix-2 Stockham FFT, 128 threads per line, shared twiddle table W[128]:
// W[m] = (cos(pi*m/128), sin(pi*m/128)). sign = -1 fwd, +1 inv (unnormalized).
__device__ __forceinline__ void fft256(float2* bufA, float2* bufB,
                                       const float2* __restrict__ W,
                                       int j, float sign) {
    float2* x = bufA;
    float2* y = bufB;
#pragma unroll
    for (int st = 0; st < 8; st++) {
        int Ns = 1 << st;
        float2 v0 = x[j];
        float2 v1 = x[j + 128];
        int k = j & (Ns - 1);
        float2 w = W[k << (7 - st)];
        float wy = sign * w.y;           // exp(sign*i*theta)
        float2 tv = make_float2(v1.x * w.x - v1.y * wy,
                                v1.x * wy + v1.y * w.x);
        int id = ((j - k) << 1) + k;
        y[id]      = make_float2(v0.x + tv.x, v0.y + tv.y);
        y[id + Ns] = make_float2(v0.x - tv.x, v0.y - tv.y);
        __syncthreads();
        float2* t = x; x = y; y = t;
    }
}

__device__ __forceinline__ void fill_twiddles(float2* W, int tid) {
    if (tid < 128) {
        float s, c;
        sincospif((float)tid * (1.0f / 128.0f), &s, &c);
        W[tid] = make_float2(c, s);
    }
}

// shifted-frequency coordinate: filter[(k+128)%256] of linspace(-127.5..127.5)/128
__device__ __forceinline__ float freq_coord(int k) {
    return (k < 128) ? (k + 0.5f) * (1.0f / 128.0f)
                     : (k - 255.5f) * (1.0f / 128.0f);
}

// i0e(x) = exp(-x)*I0(x), x in [0, ~1800]
__device__ float i0e_dev(float x) {
    if (x > 8.0f) {
        float invx = 1.0f / x;
        float term = 1.0f, sum = 1.0f;
#pragma unroll
        for (int k = 1; k <= 6; k++) {
            float tk = (float)(2 * k - 1);
            term *= tk * tk * invx * (1.0f / (8.0f * (float)k));
            sum  += term;
        }
        return sum * rsqrtf(2.0f * PI_F * x);
    } else {
        float q = 0.25f * x * x;
        float term = 1.0f, sum = 1.0f;
#pragma unroll
        for (int k = 1; k <= 22; k++) {
            float ik = 1.0f / (float)k;
            term *= q * ik * ik;
            sum  += term;
        }
        return sum * __expf(-x);
    }
}

// ---------------- kernels ----------------
__global__ void k_bp(const float* __restrict__ proj, const float* __restrict__ tof,
                     const float* __restrict__ x1l, const float* __restrict__ y1l,
                     const float* __restrict__ x1r, const float* __restrict__ y1r,
                     const float* __restrict__ x2l, const float* __restrict__ y2l,
                     const float* __restrict__ x2r, const float* __restrict__ y2r,
                     int n) {
    int e = blockIdx.x * blockDim.x + threadIdx.x;
    if (e >= n) return;

    float x1 = 0.5f * (x1l[e] + x1r[e]);
    float y1 = 0.5f * (y1l[e] + y1r[e]);
    float x2 = 0.5f * (x2l[e] + x2r[e]);
    float y2 = 0.5f * (y2l[e] + y2r[e]);
    float ddx = x2 - x1, ddy = y2 - y1;
    float L = sqrtf(ddx * ddx + ddy * ddy);

    float step     = L * (1.0f / (float)PNS);
    float inv_step = (float)PNS / L;
    float center   = 0.5f * L + 0.15f * tof[e];

    // Gaussian support window
    float lo = (center - WIN_NSIG * SIGMA_MM) * inv_step - 0.5f;
    float hi = (center + WIN_NSIG * SIGMA_MM) * inv_step - 0.5f;
    int i0 = max(0,   (int)ceilf(lo));
    int i1 = min(127, (int)floorf(hi));
    if (i0 > i1) return;

    // incremental Gaussian weight: w_{i+1} = w_i * r_i ; r_{i+1} = r_i * c
    float dz = step * INV_SIGMA;
    float z0 = (((float)i0 + 0.5f) * step - center) * INV_SIGMA;
    float w  = proj[e] * step * __expf(-0.5f * z0 * z0);
    float r  = __expf(-dz * (z0 + 0.5f * dz));
    float c  = __expf(-dz * dz);

    // t advanced incrementally — EXACT in fp32 (all values are (2i+1)/256).
    // Packed f32x2: identical rounding to two scalar fma.rn (bit-exact vs R5).
    float t0f = ((float)i0 + 0.5f) * (1.0f / (float)PNS);
    uint64_t t2   = pack2(t0f, t0f);
    uint64_t dt2  = pack2(1.0f / (float)PNS, 1.0f / (float)PNS);
    uint64_t dd2  = pack2(ddx, ddy);
    uint64_t xy2  = pack2(x1, y1);
    uint64_t h2   = pack2(0.5f, 0.5f);
    uint64_t b2   = pack2(128.0f, 128.0f);

#pragma unroll 8
    for (int i = i0; i <= i1; i++) {
        uint64_t pxy = fma2(t2, dd2, xy2);      // (px,py) = t*(ddx,ddy)+(x1,y1)
        uint64_t gxy = fma2(pxy, h2, b2);       // (gx,gy) = 0.5*(px,py)+128
        float gx, gy;
        unpack2(gxy, gx, gy);
        int ix = __float2int_rd(gx);
        int iy = __float2int_rd(gy);
        if ((unsigned)(ix | iy) < 256u)
            atomicAdd(&g_img[iy * PNX + ix], w);
        w *= r;  r *= c;
        t2 = add2(t2, dt2);
    }
}

// 2 rows per block: 256 threads, group g = tid>>7 handles row 2*blockIdx+g
__global__ void k_fft_rows_fwd() {
    __shared__ float2 A[2][256];
    __shared__ float2 B[2][256];
    __shared__ float2 W[128];
    int g = threadIdx.x >> 7;
    int j = threadIdx.x & 127;
    int row = blockIdx.x * 2 + g;
    fill_twiddles(W, threadIdx.x);
    A[g][j]       = make_float2(g_img[row * PNX + j],       0.0f);
    A[g][j + 128] = make_float2(g_img[row * PNX + j + 128], 0.0f);
    // re-zero accumulator for the next invocation
    g_img[row * PNX + j]       = 0.0f;
    g_img[row * PNX + j + 128] = 0.0f;
    __syncthreads();
    fft256(A[g], B[g], W, j, -1.0f);
    g_freq[row * PNX + j]       = A[g][j];
    g_freq[row * PNX + j + 128] = A[g][j + 128];
}

// fused: column fwd FFT -> TOF deblur filter (+scalars) -> column inv FFT
__global__ void k_fft_cols_filter() {
    __shared__ float2 A[2][256];
    __shared__ float2 B[2][256];
    __shared__ float2 W[128];
    int g = threadIdx.x >> 7;
    int j = threadIdx.x & 127;
    int c = blockIdx.x * 2 + g;
    fill_twiddles(W, threadIdx.x);
    A[g][j]       = g_freq[j * PNX + c];
    A[g][j + 128] = g_freq[(j + 128) * PNX + c];
    __syncthreads();
    fft256(A[g], B[g], W, j, -1.0f);

    float fc  = freq_coord(c);
    float fc2 = fc * fc;
#pragma unroll
    for (int kk = j; kk < 256; kk += 128) {
        float fr = freq_coord(kk);
        float w0 = fmaf(fr, fr, fc2);
        float gn = FILT_SCALE / i0e_dev(w0 * FILT_C2);
        A[g][kk].x *= gn;
        A[g][kk].y *= gn;
    }
    __syncthreads();
    fft256(A[g], B[g], W, j, +1.0f);
    g_freq[j * PNX + c]         = A[g][j];
    g_freq[(j + 128) * PNX + c] = A[g][j + 128];
}

__global__ void k_fft_rows_inv(float* __restrict__ out) {
    __shared__ float2 A[2][256];
    __shared__ float2 B[2][256];
    __shared__ float2 W[128];
    int g = threadIdx.x >> 7;
    int j = threadIdx.x & 127;
    int row = blockIdx.x * 2 + g;
    fill_twiddles(W, threadIdx.x);
    A[g][j]       = g_freq[row * PNX + j];
    A[g][j + 128] = g_freq[row * PNX + j + 128];
    __syncthreads();
    fft256(A[g], B[g], W, j, +1.0f);
    out[row * PNX + j]       = A[g][j].x;
    out[row * PNX + j + 128] = A[g][j + 128].x;
}

// ---------------- launch ----------------
extern "C" void kernel_launch(void* const* d_in, const int* in_sizes, int n_in,
                              void* d_out, int out_size) {
    const float* proj = (const float*)d_in[0];
    const float* tof  = (const float*)d_in[1];
    const float* x1l  = (const float*)d_in[2];
    const float* y1l  = (const float*)d_in[3];
    const float* x1r  = (const float*)d_in[4];
    const float* y1r  = (const float*)d_in[5];
    const float* x2l  = (const float*)d_in[6];
    const float* y2l  = (const float*)d_in[7];
    const float* x2r  = (const float*)d_in[8];
    const float* y2r  = (const float*)d_in[9];
    int n = in_sizes[0];

    k_bp<<<(n + 255) / 256, 256>>>(proj, tof, x1l, y1l, x1r, y1r,
                                   x2l, y2l, x2r, y2r, n);
    k_fft_rows_fwd<<<PNX / 2, 256>>>();
    k_fft_cols_filter<<<PNX / 2, 256>>>();
    k_fft_rows_inv<<<PNX / 2, 256>>>((float*)d_out);
}

// round 7
// speedup vs baseline: 2.1280x; 1.5481x over previous
#include <cuda_runtime.h>
#include <cstdint>

// ---------------- static config ----------------
#define PNX 256
#define PNS 128
#define PI_F 3.14159265358979323846f

#define SIGMA_MM   19.108280254777070f
#define INV_SIGMA  (1.0f/19.108280254777070f)
#define FILT_C2    900.91346f
#define FILT_SCALE (1.0f/1024.0f)
#define WIN_NSIG   3.5f
#define NREP       4
#define FFT_BLOCKS 128   // 2 lines per block; 128 < 148 SMs -> co-resident

// ---------------- device scratch ----------------
__device__ float  g_img[NREP][PNX * PNX];   // zero-init at load; re-zeroed each call
__device__ float2 g_freq[PNX * PNX];
__device__ unsigned g_bar_count = 0;
__device__ volatile unsigned g_bar_gen = 0;

// ---------------- packed f32x2 helpers (sm_100a) ----------------
__device__ __forceinline__ uint64_t pack2(float lo, float hi) {
    uint64_t r; asm("mov.b64 %0, {%1, %2};" : "=l"(r) : "f"(lo), "f"(hi)); return r;
}
__device__ __forceinline__ void unpack2(uint64_t v, float& lo, float& hi) {
    asm("mov.b64 {%0, %1}, %2;" : "=f"(lo), "=f"(hi) : "l"(v));
}
__device__ __forceinline__ uint64_t fma2(uint64_t a, uint64_t b, uint64_t c) {
    uint64_t r; asm("fma.rn.f32x2 %0, %1, %2, %3;" : "=l"(r) : "l"(a), "l"(b), "l"(c)); return r;
}
__device__ __forceinline__ uint64_t add2(uint64_t a, uint64_t b) {
    uint64_t r; asm("add.rn.f32x2 %0, %1, %2;" : "=l"(r) : "l"(a), "l"(b)); return r;
}

// ---------------- grid barrier (all blocks co-resident) ----------------
__device__ __forceinline__ void grid_barrier(unsigned nblocks) {
    __syncthreads();
    if (threadIdx.x == 0) {
        unsigned gen = g_bar_gen;
        __threadfence();                         // release prior global writes
        if (atomicAdd(&g_bar_count, 1u) == nblocks - 1u) {
            g_bar_count = 0;
            __threadfence();
            g_bar_gen = gen + 1u;                // release
        } else {
            while (g_bar_gen == gen) { }         // volatile spin
            __threadfence();                     // acquire
        }
    }
    __syncthreads();
}

// ---------------- FFT helpers ----------------
// 256-pt radix-2 Stockham FFT, 128 threads per line, shared twiddles W[128].
__device__ __forceinline__ void fft256(float2* bufA, float2* bufB,
                                       const float2* __restrict__ W,
                                       int j, float sign) {
    float2* x = bufA;
    float2* y = bufB;
#pragma unroll
    for (int st = 0; st < 8; st++) {
        int Ns = 1 << st;
        float2 v0 = x[j];
        float2 v1 = x[j + 128];
        int k = j & (Ns - 1);
        float2 w = W[k << (7 - st)];
        float wy = sign * w.y;
        float2 tv = make_float2(v1.x * w.x - v1.y * wy,
                                v1.x * wy + v1.y * w.x);
        int id = ((j - k) << 1) + k;
        y[id]      = make_float2(v0.x + tv.x, v0.y + tv.y);
        y[id + Ns] = make_float2(v0.x - tv.x, v0.y - tv.y);
        __syncthreads();
        float2* t = x; x = y; y = t;
    }
}

__device__ __forceinline__ void fill_twiddles(float2* W, int tid) {
    if (tid < 128) {
        float s, c;
        sincospif((float)tid * (1.0f / 128.0f), &s, &c);
        W[tid] = make_float2(c, s);
    }
}

__device__ __forceinline__ float freq_coord(int k) {
    return (k < 128) ? (k + 0.5f) * (1.0f / 128.0f)
                     : (k - 255.5f) * (1.0f / 128.0f);
}

// i0e(x) = exp(-x)*I0(x)
__device__ float i0e_dev(float x) {
    if (x > 8.0f) {
        float invx = 1.0f / x;
        float term = 1.0f, sum = 1.0f;
#pragma unroll
        for (int k = 1; k <= 6; k++) {
            float tk = (float)(2 * k - 1);
            term *= tk * tk * invx * (1.0f / (8.0f * (float)k));
            sum  += term;
        }
        return sum * rsqrtf(2.0f * PI_F * x);
    } else {
        float q = 0.25f * x * x;
        float term = 1.0f, sum = 1.0f;
#pragma unroll
        for (int k = 1; k <= 22; k++) {
            float ik = 1.0f / (float)k;
            term *= q * ik * ik;
            sum  += term;
        }
        return sum * __expf(-x);
    }
}

// ---------------- backprojection ----------------
__global__ void k_bp(const float* __restrict__ proj, const float* __restrict__ tof,
                     const float* __restrict__ x1l, const float* __restrict__ y1l,
                     const float* __restrict__ x1r, const float* __restrict__ y1r,
                     const float* __restrict__ x2l, const float* __restrict__ y2l,
                     const float* __restrict__ x2r, const float* __restrict__ y2r,
                     int n) {
    int e = blockIdx.x * blockDim.x + threadIdx.x;
    if (e >= n) return;

    float x1 = 0.5f * (x1l[e] + x1r[e]);
    float y1 = 0.5f * (y1l[e] + y1r[e]);
    float x2 = 0.5f * (x2l[e] + x2r[e]);
    float y2 = 0.5f * (y2l[e] + y2r[e]);
    float ddx = x2 - x1, ddy = y2 - y1;
    float L = sqrtf(ddx * ddx + ddy * ddy);

    float step     = L * (1.0f / (float)PNS);
    float inv_step = (float)PNS / L;
    float center   = 0.5f * L + 0.15f * tof[e];

    float lo = (center - WIN_NSIG * SIGMA_MM) * inv_step - 0.5f;
    float hi = (center + WIN_NSIG * SIGMA_MM) * inv_step - 0.5f;
    int i0 = max(0,   (int)ceilf(lo));
    int i1 = min(127, (int)floorf(hi));
    if (i0 > i1) return;

    // incremental Gaussian weight
    float dz = step * INV_SIGMA;
    float z0 = (((float)i0 + 0.5f) * step - center) * INV_SIGMA;
    float w  = proj[e] * step * __expf(-0.5f * z0 * z0);
    float r  = __expf(-dz * (z0 + 0.5f * dz));
    float c  = __expf(-dz * dz);

    float* img = g_img[e & (NREP - 1)];   // de-contend hot pixels 4-way

    float t0f = ((float)i0 + 0.5f) * (1.0f / (float)PNS);
    uint64_t t2   = pack2(t0f, t0f);
    uint64_t dt2  = pack2(1.0f / (float)PNS, 1.0f / (float)PNS);
    uint64_t dd2  = pack2(ddx, ddy);
    uint64_t xy2  = pack2(x1, y1);
    uint64_t h2   = pack2(0.5f, 0.5f);
    uint64_t b2   = pack2(128.0f, 128.0f);

#pragma unroll 8
    for (int i = i0; i <= i1; i++) {
        uint64_t pxy = fma2(t2, dd2, xy2);
        uint64_t gxy = fma2(pxy, h2, b2);
        float gx, gy;
        unpack2(gxy, gx, gy);
        int ix = __float2int_rd(gx);
        int iy = __float2int_rd(gy);
        if ((unsigned)(ix | iy) < 256u)
            atomicAdd(&img[iy * PNX + ix], w);
        w *= r;  r *= c;
        t2 = add2(t2, dt2);
    }
}

// ---------------- fused 2D FFT + filter (persistent, grid barrier) ----------------
// 128 blocks x 256 threads; group g = tid>>7 handles line 2*blockIdx+g.
__global__ void k_fft_all(float* __restrict__ out) {
    __shared__ float2 A[2][256];
    __shared__ float2 B[2][256];
    __shared__ float2 W[128];
    int g = threadIdx.x >> 7;
    int j = threadIdx.x & 127;
    int line = blockIdx.x * 2 + g;
    fill_twiddles(W, threadIdx.x);

    // ---- Phase A: row forward FFT (sum replicas, re-zero accumulators) ----
    {
        int row = line;
#pragma unroll
        for (int half = 0; half < 2; half++) {
            int col = j + half * 128;
            int idx = row * PNX + col;
            float v = g_img[0][idx] + g_img[1][idx] + g_img[2][idx] + g_img[3][idx];
            A[g][col] = make_float2(v, 0.0f);
            g_img[0][idx] = 0.0f; g_img[1][idx] = 0.0f;
            g_img[2][idx] = 0.0f; g_img[3][idx] = 0.0f;
        }
        __syncthreads();
        fft256(A[g], B[g], W, j, -1.0f);
        g_freq[row * PNX + j]       = A[g][j];
        g_freq[row * PNX + j + 128] = A[g][j + 128];
    }

    grid_barrier(FFT_BLOCKS);

    // ---- Phase B: column fwd FFT -> filter -> column inv FFT ----
    {
        int c = line;
        A[g][j]       = __ldcg(&g_freq[j * PNX + c]);           // bypass stale L1
        A[g][j + 128] = __ldcg(&g_freq[(j + 128) * PNX + c]);
        __syncthreads();
        fft256(A[g], B[g], W, j, -1.0f);

        float fc  = freq_coord(c);
        float fc2 = fc * fc;
#pragma unroll
        for (int kk = j; kk < 256; kk += 128) {
            float fr = freq_coord(kk);
            float w0 = fmaf(fr, fr, fc2);
            float gn = FILT_SCALE / i0e_dev(w0 * FILT_C2);
            A[g][kk].x *= gn;
            A[g][kk].y *= gn;
        }
        __syncthreads();
        fft256(A[g], B[g], W, j, +1.0f);
        g_freq[j * PNX + c]         = A[g][j];
        g_freq[(j + 128) * PNX + c] = A[g][j + 128];
    }

    grid_barrier(FFT_BLOCKS);

    // ---- Phase C: row inverse FFT -> real output ----
    {
        int row = line;
        A[g][j]       = __ldcg(&g_freq[row * PNX + j]);         // bypass stale L1
        A[g][j + 128] = __ldcg(&g_freq[row * PNX + j + 128]);
        __syncthreads();
        fft256(A[g], B[g], W, j, +1.0f);
        out[row * PNX + j]       = A[g][j].x;
        out[row * PNX + j + 128] = A[g][j + 128].x;
    }
}

// ---------------- launch ----------------
extern "C" void kernel_launch(void* const* d_in, const int* in_sizes, int n_in,
                              void* d_out, int out_size) {
    const float* proj = (const float*)d_in[0];
    const float* tof  = (const float*)d_in[1];
    const float* x1l  = (const float*)d_in[2];
    const float* y1l  = (const float*)d_in[3];
    const float* x1r  = (const float*)d_in[4];
    const float* y1r  = (const float*)d_in[5];
    const float* x2l  = (const float*)d_in[6];
    const float* y2l  = (const float*)d_in[7];
    const float* x2r  = (const float*)d_in[8];
    const float* y2r  = (const float*)d_in[9];
    int n = in_sizes[0];

    k_bp<<<(n + 255) / 256, 256>>>(proj, tof, x1l, y1l, x1r, y1r,
                                   x2l, y2l, x2r, y2r, n);
    k_fft_all<<<FFT_BLOCKS, 256>>>((float*)d_out);
}

// round 8
// speedup vs baseline: 2.4444x; 1.1487x over previous
#include <cuda_runtime.h>
#include <cstdint>

// ---------------- static config ----------------
#define PNX 256
#define PNS 128
#define PI_F 3.14159265358979323846f

#define SIGMA_MM   19.108280254777070f
#define INV_SIGMA  (1.0f/19.108280254777070f)
#define FILT_C2    900.91346f
#define FILT_SCALE (1.0f/1024.0f)
#define WIN_NSIG   3.5f
#define NREP       16
#define FFT_BLOCKS 128   // 2 lines/block, 128 < 148 SMs -> co-resident

// ---------------- device scratch ----------------
__device__ float  g_img[NREP][PNX * PNX];   // zero-init at load; re-zeroed each call
__device__ float2 g_freq[PNX * PNX];
__device__ unsigned g_bar_count = 0;
__device__ volatile unsigned g_bar_gen = 0;

// ---------------- packed f32x2 helpers (sm_100a) ----------------
__device__ __forceinline__ uint64_t pack2(float lo, float hi) {
    uint64_t r; asm("mov.b64 %0, {%1, %2};" : "=l"(r) : "f"(lo), "f"(hi)); return r;
}
__device__ __forceinline__ void unpack2(uint64_t v, float& lo, float& hi) {
    asm("mov.b64 {%0, %1}, %2;" : "=f"(lo), "=f"(hi) : "l"(v));
}
__device__ __forceinline__ uint64_t fma2(uint64_t a, uint64_t b, uint64_t c) {
    uint64_t r; asm("fma.rn.f32x2 %0, %1, %2, %3;" : "=l"(r) : "l"(a), "l"(b), "l"(c)); return r;
}
__device__ __forceinline__ uint64_t add2(uint64_t a, uint64_t b) {
    uint64_t r; asm("add.rn.f32x2 %0, %1, %2;" : "=l"(r) : "l"(a), "l"(b)); return r;
}

// ---------------- grid barrier (all blocks co-resident) ----------------
__device__ __forceinline__ void grid_barrier(unsigned nblocks) {
    __syncthreads();
    if (threadIdx.x == 0) {
        unsigned gen = g_bar_gen;
        __threadfence();
        if (atomicAdd(&g_bar_count, 1u) == nblocks - 1u) {
            g_bar_count = 0;
            __threadfence();
            g_bar_gen = gen + 1u;
        } else {
            while (g_bar_gen == gen) { }
            __threadfence();
        }
    }
    __syncthreads();
}

// ---------------- FFT helpers ----------------
__device__ __forceinline__ float2 cmul(float2 v, float wx, float wy) {
    return make_float2(v.x * wx - v.y * wy, v.x * wy + v.y * wx);
}

// 256-pt radix-4 Stockham FFT, 64 threads per line (j in [0,64)).
// Exactly equivalent to two fused radix-2 Stockham stages per step (verified
// algebraically): w1=cis(s*2pi*k/4Ns), w2=w1^2, w3=w1^3;
// y0=t0+t2 -> base, y1=t1+s*i*t3 -> +Ns, y2=t0-t2 -> +2Ns, y3=t1-s*i*t3 -> +3Ns.
// W[m] = cis(2*pi*m/256), m in [0,192). Ends in bufA after 4 stages.
__device__ __forceinline__ void fft256_r4(float2* bufA, float2* bufB,
                                          const float2* __restrict__ W,
                                          int j, float sign) {
    float2* x = bufA;
    float2* y = bufB;
#pragma unroll
    for (int st = 0; st < 4; st++) {
        int Ns = 1 << (2 * st);              // 1,4,16,64
        int k  = j & (Ns - 1);
        int m  = k * (64 >> (2 * st));       // k * 64/Ns
        float2 a0 = x[j];
        float2 a1 = x[j + 64];
        float2 a2 = x[j + 128];
        float2 a3 = x[j + 192];
        float2 w1 = W[m], w2 = W[2 * m], w3 = W[3 * m];
        float2 b1 = cmul(a1, w1.x, sign * w1.y);
        float2 c1 = cmul(a2, w2.x, sign * w2.y);
        float2 d1 = cmul(a3, w3.x, sign * w3.y);
        float2 t0 = make_float2(a0.x + c1.x, a0.y + c1.y);
        float2 t1 = make_float2(a0.x - c1.x, a0.y - c1.y);
        float2 t2 = make_float2(b1.x + d1.x, b1.y + d1.y);
        float2 t3 = make_float2(b1.x - d1.x, b1.y - d1.y);
        float2 it3 = make_float2(-sign * t3.y, sign * t3.x);   // s*i*t3
        int base = ((j - k) << 2) + k;
        y[base]          = make_float2(t0.x + t2.x, t0.y + t2.y);
        y[base + Ns]     = make_float2(t1.x + it3.x, t1.y + it3.y);
        y[base + 2 * Ns] = make_float2(t0.x - t2.x, t0.y - t2.y);
        y[base + 3 * Ns] = make_float2(t1.x - it3.x, t1.y - it3.y);
        __syncthreads();
        float2* t = x; x = y; y = t;
    }
}

__device__ __forceinline__ void fill_twiddles192(float2* W, int tid) {
    for (int m = tid; m < 192; m += 128) {
        float s, c;
        sincospif((float)m * (1.0f / 128.0f), &s, &c);
        W[m] = make_float2(c, s);
    }
}

__device__ __forceinline__ float freq_coord(int k) {
    return (k < 128) ? (k + 0.5f) * (1.0f / 128.0f)
                     : (k - 255.5f) * (1.0f / 128.0f);
}

// i0e(x) = exp(-x)*I0(x)
__device__ float i0e_dev(float x) {
    if (x > 8.0f) {
        float invx = 1.0f / x;
        float term = 1.0f, sum = 1.0f;
#pragma unroll
        for (int k = 1; k <= 6; k++) {
            float tk = (float)(2 * k - 1);
            term *= tk * tk * invx * (1.0f / (8.0f * (float)k));
            sum  += term;
        }
        return sum * rsqrtf(2.0f * PI_F * x);
    } else {
        float q = 0.25f * x * x;
        float term = 1.0f, sum = 1.0f;
#pragma unroll
        for (int k = 1; k <= 22; k++) {
            float ik = 1.0f / (float)k;
            term *= q * ik * ik;
            sum  += term;
        }
        return sum * __expf(-x);
    }
}

// ---------------- backprojection ----------------
__global__ void k_bp(const float* __restrict__ proj, const float* __restrict__ tof,
                     const float* __restrict__ x1l, const float* __restrict__ y1l,
                     const float* __restrict__ x1r, const float* __restrict__ y1r,
                     const float* __restrict__ x2l, const float* __restrict__ y2l,
                     const float* __restrict__ x2r, const float* __restrict__ y2r,
                     int n) {
    int e = blockIdx.x * blockDim.x + threadIdx.x;
    if (e >= n) return;

    float x1 = 0.5f * (x1l[e] + x1r[e]);
    float y1 = 0.5f * (y1l[e] + y1r[e]);
    float x2 = 0.5f * (x2l[e] + x2r[e]);
    float y2 = 0.5f * (y2l[e] + y2r[e]);
    float ddx = x2 - x1, ddy = y2 - y1;
    float L = sqrtf(ddx * ddx + ddy * ddy);

    float step     = L * (1.0f / (float)PNS);
    float inv_step = (float)PNS / L;
    float center   = 0.5f * L + 0.15f * tof[e];

    float lo = (center - WIN_NSIG * SIGMA_MM) * inv_step - 0.5f;
    float hi = (center + WIN_NSIG * SIGMA_MM) * inv_step - 0.5f;
    int i0 = max(0,   (int)ceilf(lo));
    int i1 = min(127, (int)floorf(hi));
    if (i0 > i1) return;

    // incremental Gaussian weight
    float dz = step * INV_SIGMA;
    float z0 = (((float)i0 + 0.5f) * step - center) * INV_SIGMA;
    float w  = proj[e] * step * __expf(-0.5f * z0 * z0);
    float r  = __expf(-dz * (z0 + 0.5f * dz));
    float c  = __expf(-dz * dz);

    float* img = g_img[e & (NREP - 1)];   // de-contend hot pixels 16-way

    float t0f = ((float)i0 + 0.5f) * (1.0f / (float)PNS);
    uint64_t t2   = pack2(t0f, t0f);
    uint64_t dt2  = pack2(1.0f / (float)PNS, 1.0f / (float)PNS);
    uint64_t dd2  = pack2(ddx, ddy);
    uint64_t xy2  = pack2(x1, y1);
    uint64_t h2   = pack2(0.5f, 0.5f);
    uint64_t b2   = pack2(128.0f, 128.0f);

#pragma unroll 8
    for (int i = i0; i <= i1; i++) {
        uint64_t pxy = fma2(t2, dd2, xy2);
        uint64_t gxy = fma2(pxy, h2, b2);
        float gx, gy;
        unpack2(gxy, gx, gy);
        int ix = __float2int_rd(gx);
        int iy = __float2int_rd(gy);
        if ((unsigned)(ix | iy) < 256u)
            atomicAdd(&img[iy * PNX + ix], w);
        w *= r;  r *= c;
        t2 = add2(t2, dt2);
    }
}

// ---------------- fused 2D FFT + filter (persistent, grid barrier) ----------------
// 128 blocks x 128 threads; group g = tid>>6 handles line 2*blockIdx+g, j = tid&63.
__global__ void k_fft_all(float* __restrict__ out) {
    __shared__ float2 A[2][256];
    __shared__ float2 B[2][256];
    __shared__ float2 W[192];
    int g = threadIdx.x >> 6;
    int j = threadIdx.x & 63;
    int line = blockIdx.x * 2 + g;
    fill_twiddles192(W, threadIdx.x);

    // ---- Phase A: row forward FFT (sum 16 replicas via float4, re-zero) ----
    {
        int row = line;
        int c4 = 4 * j;                       // 4 consecutive columns
        float4* base = (float4*)&g_img[0][row * PNX + c4];
        const int stride4 = (PNX * PNX) / 4;  // float4 stride between replicas
        float4 acc = make_float4(0.f, 0.f, 0.f, 0.f);
#pragma unroll
        for (int rep = 0; rep < NREP; rep++) {
            float4 v = base[rep * stride4];
            acc.x += v.x; acc.y += v.y; acc.z += v.z; acc.w += v.w;
            base[rep * stride4] = make_float4(0.f, 0.f, 0.f, 0.f);
        }
        A[g][c4]     = make_float2(acc.x, 0.0f);
        A[g][c4 + 1] = make_float2(acc.y, 0.0f);
        A[g][c4 + 2] = make_float2(acc.z, 0.0f);
        A[g][c4 + 3] = make_float2(acc.w, 0.0f);
        __syncthreads();
        fft256_r4(A[g], B[g], W, j, -1.0f);
#pragma unroll
        for (int q = 0; q < 4; q++)
            g_freq[row * PNX + j + q * 64] = A[g][j + q * 64];
    }

    grid_barrier(FFT_BLOCKS);

    // ---- Phase B: column fwd FFT -> filter -> column inv FFT ----
    {
        int c = line;
#pragma unroll
        for (int q = 0; q < 4; q++)
            A[g][j + q * 64] = __ldcg(&g_freq[(j + q * 64) * PNX + c]);
        __syncthreads();
        fft256_r4(A[g], B[g], W, j, -1.0f);

        float fc  = freq_coord(c);
        float fc2 = fc * fc;
#pragma unroll
        for (int kk = j; kk < 256; kk += 64) {
            float fr = freq_coord(kk);
            float w0 = fmaf(fr, fr, fc2);
            float gn = FILT_SCALE / i0e_dev(w0 * FILT_C2);
            A[g][kk].x *= gn;
            A[g][kk].y *= gn;
        }
        __syncthreads();
        fft256_r4(A[g], B[g], W, j, +1.0f);
#pragma unroll
        for (int q = 0; q < 4; q++)
            g_freq[(j + q * 64) * PNX + c] = A[g][j + q * 64];
    }

    grid_barrier(FFT_BLOCKS);

    // ---- Phase C: row inverse FFT -> real output ----
    {
        int row = line;
#pragma unroll
        for (int q = 0; q < 4; q++)
            A[g][j + q * 64] = __ldcg(&g_freq[row * PNX + j + q * 64]);
        __syncthreads();
        fft256_r4(A[g], B[g], W, j, +1.0f);
#pragma unroll
        for (int q = 0; q < 4; q++)
            out[row * PNX + j + q * 64] = A[g][j + q * 64].x;
    }
}

// ---------------- launch ----------------
extern "C" void kernel_launch(void* const* d_in, const int* in_sizes, int n_in,
                              void* d_out, int out_size) {
    const float* proj = (const float*)d_in[0];
    const float* tof  = (const float*)d_in[1];
    const float* x1l  = (const float*)d_in[2];
    const float* y1l  = (const float*)d_in[3];
    const float* x1r  = (const float*)d_in[4];
    const float* y1r  = (const float*)d_in[5];
    const float* x2l  = (const float*)d_in[6];
    const float* y2l  = (const float*)d_in[7];
    const float* x2r  = (const float*)d_in[8];
    const float* y2r  = (const float*)d_in[9];
    int n = in_sizes[0];

    k_bp<<<(n + 255) / 256, 256>>>(proj, tof, x1l, y1l, x1r, y1r,
                                   x2l, y2l, x2r, y2r, n);
    k_fft_all<<<FFT_BLOCKS, 128>>>((float*)d_out);
}

// round 9
// speedup vs baseline: 2.4558x; 1.0047x over previous
#include <cuda_runtime.h>
#include <cstdint>

// ---------------- static config ----------------
#define PNX 256
#define PNS 128
#define PI_F 3.14159265358979323846f

#define SIGMA_MM   19.108280254777070f
#define INV_SIGMA  (1.0f/19.108280254777070f)
#define FILT_C2    900.91346f
#define FILT_SCALE (1.0f/1024.0f)
#define WIN_NSIG   3.5f
#define NREP       32
#define FFT_BLOCKS 64    // 4 lines/block, 64 < 148 SMs -> co-resident

// ---------------- device scratch ----------------
__device__ float  g_img[NREP][PNX * PNX];   // zero-init at load; re-zeroed each call
__device__ float2 g_freqT[PNX * PNX];       // row-spectrum, TRANSPOSED [colfreq][row]
__device__ float2 g_freq[PNX * PNX];        // filtered spectrum [row][colfreq]
__device__ unsigned g_bar_count = 0;
__device__ volatile unsigned g_bar_gen = 0;

// ---------------- packed f32x2 helpers (sm_100a) ----------------
__device__ __forceinline__ uint64_t pack2(float lo, float hi) {
    uint64_t r; asm("mov.b64 %0, {%1, %2};" : "=l"(r) : "f"(lo), "f"(hi)); return r;
}
__device__ __forceinline__ void unpack2(uint64_t v, float& lo, float& hi) {
    asm("mov.b64 {%0, %1}, %2;" : "=f"(lo), "=f"(hi) : "l"(v));
}
__device__ __forceinline__ uint64_t fma2(uint64_t a, uint64_t b, uint64_t c) {
    uint64_t r; asm("fma.rn.f32x2 %0, %1, %2, %3;" : "=l"(r) : "l"(a), "l"(b), "l"(c)); return r;
}
__device__ __forceinline__ uint64_t add2(uint64_t a, uint64_t b) {
    uint64_t r; asm("add.rn.f32x2 %0, %1, %2;" : "=l"(r) : "l"(a), "l"(b)); return r;
}

// ---------------- grid barrier (all blocks co-resident) ----------------
__device__ __forceinline__ void grid_barrier(unsigned nblocks) {
    __syncthreads();
    if (threadIdx.x == 0) {
        unsigned gen = g_bar_gen;
        __threadfence();
        if (atomicAdd(&g_bar_count, 1u) == nblocks - 1u) {
            g_bar_count = 0;
            __threadfence();
            g_bar_gen = gen + 1u;
        } else {
            while (g_bar_gen == gen) { }
            __threadfence();
        }
    }
    __syncthreads();
}

// ---------------- FFT helpers ----------------
__device__ __forceinline__ float2 cmul(float2 v, float wx, float wy) {
    return make_float2(v.x * wx - v.y * wy, v.x * wy + v.y * wx);
}

// 256-pt radix-4 Stockham FFT, 64 threads per line (j in [0,64)).
// W[m] = cis(2*pi*m/256), m in [0,192). Ends in bufA after 4 stages.
__device__ __forceinline__ void fft256_r4(float2* bufA, float2* bufB,
                                          const float2* __restrict__ W,
                                          int j, float sign) {
    float2* x = bufA;
    float2* y = bufB;
#pragma unroll
    for (int st = 0; st < 4; st++) {
        int Ns = 1 << (2 * st);              // 1,4,16,64
        int k  = j & (Ns - 1);
        int m  = k * (64 >> (2 * st));       // k * 64/Ns
        float2 a0 = x[j];
        float2 a1 = x[j + 64];
        float2 a2 = x[j + 128];
        float2 a3 = x[j + 192];
        float2 w1 = W[m], w2 = W[2 * m], w3 = W[3 * m];
        float2 b1 = cmul(a1, w1.x, sign * w1.y);
        float2 c1 = cmul(a2, w2.x, sign * w2.y);
        float2 d1 = cmul(a3, w3.x, sign * w3.y);
        float2 t0 = make_float2(a0.x + c1.x, a0.y + c1.y);
        float2 t1 = make_float2(a0.x - c1.x, a0.y - c1.y);
        float2 t2 = make_float2(b1.x + d1.x, b1.y + d1.y);
        float2 t3 = make_float2(b1.x - d1.x, b1.y - d1.y);
        float2 it3 = make_float2(-sign * t3.y, sign * t3.x);   // s*i*t3
        int base = ((j - k) << 2) + k;
        y[base]          = make_float2(t0.x + t2.x, t0.y + t2.y);
        y[base + Ns]     = make_float2(t1.x + it3.x, t1.y + it3.y);
        y[base + 2 * Ns] = make_float2(t0.x - t2.x, t0.y - t2.y);
        y[base + 3 * Ns] = make_float2(t1.x - it3.x, t1.y - it3.y);
        __syncthreads();
        float2* t = x; x = y; y = t;
    }
}

__device__ __forceinline__ void fill_twiddles192(float2* W, int tid) {
    if (tid < 192) {
        float s, c;
        sincospif((float)tid * (1.0f / 128.0f), &s, &c);
        W[tid] = make_float2(c, s);
    }
}

__device__ __forceinline__ float freq_coord(int k) {
    return (k < 128) ? (k + 0.5f) * (1.0f / 128.0f)
                     : (k - 255.5f) * (1.0f / 128.0f);
}

// i0e(x) = exp(-x)*I0(x)
__device__ float i0e_dev(float x) {
    if (x > 8.0f) {
        float invx = 1.0f / x;
        float term = 1.0f, sum = 1.0f;
#pragma unroll
        for (int k = 1; k <= 6; k++) {
            float tk = (float)(2 * k - 1);
            term *= tk * tk * invx * (1.0f / (8.0f * (float)k));
            sum  += term;
        }
        return sum * rsqrtf(2.0f * PI_F * x);
    } else {
        float q = 0.25f * x * x;
        float term = 1.0f, sum = 1.0f;
#pragma unroll
        for (int k = 1; k <= 22; k++) {
            float ik = 1.0f / (float)k;
            term *= q * ik * ik;
            sum  += term;
        }
        return sum * __expf(-x);
    }
}

// ---------------- backprojection ----------------
__global__ void k_bp(const float* __restrict__ proj, const float* __restrict__ tof,
                     const float* __restrict__ x1l, const float* __restrict__ y1l,
                     const float* __restrict__ x1r, const float* __restrict__ y1r,
                     const float* __restrict__ x2l, const float* __restrict__ y2l,
                     const float* __restrict__ x2r, const float* __restrict__ y2r,
                     int n) {
    int e = blockIdx.x * blockDim.x + threadIdx.x;
    if (e >= n) return;

    float x1 = 0.5f * (x1l[e] + x1r[e]);
    float y1 = 0.5f * (y1l[e] + y1r[e]);
    float x2 = 0.5f * (x2l[e] + x2r[e]);
    float y2 = 0.5f * (y2l[e] + y2r[e]);
    float ddx = x2 - x1, ddy = y2 - y1;
    float L = sqrtf(ddx * ddx + ddy * ddy);

    float step     = L * (1.0f / (float)PNS);
    float inv_step = (float)PNS / L;
    float center   = 0.5f * L + 0.15f * tof[e];

    float lo = (center - WIN_NSIG * SIGMA_MM) * inv_step - 0.5f;
    float hi = (center + WIN_NSIG * SIGMA_MM) * inv_step - 0.5f;
    int i0 = max(0,   (int)ceilf(lo));
    int i1 = min(127, (int)floorf(hi));
    if (i0 > i1) return;

    // incremental Gaussian weight
    float dz = step * INV_SIGMA;
    float z0 = (((float)i0 + 0.5f) * step - center) * INV_SIGMA;
    float w  = proj[e] * step * __expf(-0.5f * z0 * z0);
    float r  = __expf(-dz * (z0 + 0.5f * dz));
    float c  = __expf(-dz * dz);

    float* img = g_img[e & (NREP - 1)];   // de-contend hot pixels 32-way

    float t0f = ((float)i0 + 0.5f) * (1.0f / (float)PNS);
    uint64_t t2   = pack2(t0f, t0f);
    uint64_t dt2  = pack2(1.0f / (float)PNS, 1.0f / (float)PNS);
    uint64_t dd2  = pack2(ddx, ddy);
    uint64_t xy2  = pack2(x1, y1);
    uint64_t h2   = pack2(0.5f, 0.5f);
    uint64_t b2   = pack2(128.0f, 128.0f);

#pragma unroll 8
    for (int i = i0; i <= i1; i++) {
        uint64_t pxy = fma2(t2, dd2, xy2);
        uint64_t gxy = fma2(pxy, h2, b2);
        float gx, gy;
        unpack2(gxy, gx, gy);
        int ix = __float2int_rd(gx);
        int iy = __float2int_rd(gy);
        if ((unsigned)(ix | iy) < 256u)
            atomicAdd(&img[iy * PNX + ix], w);
        w *= r;  r *= c;
        t2 = add2(t2, dt2);
    }
}

// ---------------- fused 2D FFT + filter (persistent, grid barrier) ----------------
// 64 blocks x 256 threads; 4 line-groups of 64 threads: g = tid>>6, j = tid&63.
// All strided accesses are STORES (transpose-on-store); all loads coalesced.
__global__ void k_fft_all(float* __restrict__ out) {
    __shared__ float2 A[4][256];
    __shared__ float2 B[4][256];
    __shared__ float2 W[192];
    int g = threadIdx.x >> 6;
    int j = threadIdx.x & 63;
    int line = blockIdx.x * 4 + g;
    fill_twiddles192(W, threadIdx.x);

    // ---- Phase A: row forward FFT (sum 32 replicas via float4, re-zero),
    //      store spectrum TRANSPOSED: g_freqT[k*256 + row] ----
    {
        int row = line;
        float4* base = (float4*)&g_img[0][row * PNX] + j;   // 64 float4 per row
        const int stride4 = (PNX * PNX) / 4;
        float4 acc = make_float4(0.f, 0.f, 0.f, 0.f);
#pragma unroll 8
        for (int rep = 0; rep < NREP; rep++) {
            float4 v = base[rep * stride4];
            acc.x += v.x; acc.y += v.y; acc.z += v.z; acc.w += v.w;
            base[rep * stride4] = make_float4(0.f, 0.f, 0.f, 0.f);
        }
        int c4 = 4 * j;
        A[g][c4]     = make_float2(acc.x, 0.0f);
        A[g][c4 + 1] = make_float2(acc.y, 0.0f);
        A[g][c4 + 2] = make_float2(acc.z, 0.0f);
        A[g][c4 + 3] = make_float2(acc.w, 0.0f);
        __syncthreads();
        fft256_r4(A[g], B[g], W, j, -1.0f);
#pragma unroll
        for (int q = 0; q < 4; q++) {
            int k = j + q * 64;
            g_freqT[k * PNX + row] = A[g][k];               // scattered store
        }
    }

    grid_barrier(FFT_BLOCKS);

    // ---- Phase B: column fwd FFT -> filter -> column inv FFT
    //      load coalesced from g_freqT, store scattered to g_freq[r*256+c] ----
    {
        int c = line;
#pragma unroll
        for (int q = 0; q < 4; q++) {
            int k = j + q * 64;
            A[g][k] = __ldcg(&g_freqT[c * PNX + k]);        // coalesced load
        }
        __syncthreads();
        fft256_r4(A[g], B[g], W, j, -1.0f);

        float fc  = freq_coord(c);
        float fc2 = fc * fc;
#pragma unroll
        for (int kk = j; kk < 256; kk += 64) {
            float fr = freq_coord(kk);
            float w0 = fmaf(fr, fr, fc2);
            float gn = FILT_SCALE / i0e_dev(w0 * FILT_C2);
            A[g][kk].x *= gn;
            A[g][kk].y *= gn;
        }
        __syncthreads();
        fft256_r4(A[g], B[g], W, j, +1.0f);
#pragma unroll
        for (int q = 0; q < 4; q++) {
            int r = j + q * 64;
            g_freq[r * PNX + c] = A[g][r];                  // scattered store
        }
    }

    grid_barrier(FFT_BLOCKS);

    // ---- Phase C: row inverse FFT -> real output (coalesced load/store) ----
    {
        int row = line;
#pragma unroll
        for (int q = 0; q < 4; q++) {
            int k = j + q * 64;
            A[g][k] = __ldcg(&g_freq[row * PNX + k]);       // coalesced load
        }
        __syncthreads();
        fft256_r4(A[g], B[g], W, j, +1.0f);
#pragma unroll
        for (int q = 0; q < 4; q++) {
            int k = j + q * 64;
            out[row * PNX + k] = A[g][k].x;
        }
    }
}

// ---------------- launch ----------------
extern "C" void kernel_launch(void* const* d_in, const int* in_sizes, int n_in,
                              void* d_out, int out_size) {
    const float* proj = (const float*)d_in[0];
    const float* tof  = (const float*)d_in[1];
    const float* x1l  = (const float*)d_in[2];
    const float* y1l  = (const float*)d_in[3];
    const float* x1r  = (const float*)d_in[4];
    const float* y1r  = (const float*)d_in[5];
    const float* x2l  = (const float*)d_in[6];
    const float* y2l  = (const float*)d_in[7];
    const float* x2r  = (const float*)d_in[8];
    const float* y2r  = (const float*)d_in[9];
    int n = in_sizes[0];

    k_bp<<<(n + 255) / 256, 256>>>(proj, tof, x1l, y1l, x1r, y1r,
                                   x2l, y2l, x2r, y2r, n);
    k_fft_all<<<FFT_BLOCKS, 256>>>((float*)d_out);
}

// round 10
// speedup vs baseline: 2.4979x; 1.0171x over previous
#include <cuda_runtime.h>
#include <cstdint>

// ---------------- static config ----------------
#define PNX 256
#define PNS 128
#define PI_F 3.14159265358979323846f

#define SIGMA_MM   19.108280254777070f
#define INV_SIGMA  (1.0f/19.108280254777070f)
#define FILT_C2    900.91346f
#define FILT_SCALE (1.0f/1024.0f)
#define WIN_NSIG   3.5f
#define NREP       32
#define FFT_BLOCKS 128   // 2 lines/block, 128 < 148 SMs -> co-resident

// ---------------- device scratch ----------------
__device__ float  g_img[NREP][PNX * PNX];   // zero-init at load; re-zeroed each call
__device__ float2 g_freqT[PNX * PNX];       // row-spectrum, TRANSPOSED [colfreq][row]
__device__ float2 g_freq[PNX * PNX];        // filtered spectrum [row][colfreq]
__device__ unsigned g_bar_count = 0;
__device__ volatile unsigned g_bar_gen = 0;

// ---------------- packed f32x2 helpers (sm_100a) ----------------
__device__ __forceinline__ uint64_t pack2(float lo, float hi) {
    uint64_t r; asm("mov.b64 %0, {%1, %2};" : "=l"(r) : "f"(lo), "f"(hi)); return r;
}
__device__ __forceinline__ void unpack2(uint64_t v, float& lo, float& hi) {
    asm("mov.b64 {%0, %1}, %2;" : "=f"(lo), "=f"(hi) : "l"(v));
}
__device__ __forceinline__ uint64_t fma2(uint64_t a, uint64_t b, uint64_t c) {
    uint64_t r; asm("fma.rn.f32x2 %0, %1, %2, %3;" : "=l"(r) : "l"(a), "l"(b), "l"(c)); return r;
}
__device__ __forceinline__ uint64_t add2(uint64_t a, uint64_t b) {
    uint64_t r; asm("add.rn.f32x2 %0, %1, %2;" : "=l"(r) : "l"(a), "l"(b)); return r;
}

// ---------------- grid barrier (all blocks co-resident) ----------------
__device__ __forceinline__ void grid_barrier(unsigned nblocks) {
    __syncthreads();
    if (threadIdx.x == 0) {
        unsigned gen = g_bar_gen;
        __threadfence();
        if (atomicAdd(&g_bar_count, 1u) == nblocks - 1u) {
            g_bar_count = 0;
            __threadfence();
            g_bar_gen = gen + 1u;
        } else {
            while (g_bar_gen == gen) { }
            __threadfence();
        }
    }
    __syncthreads();
}

// ---------------- FFT helpers ----------------
// 256-pt radix-2 Stockham FFT, 128 threads per line, shared twiddles W[128]:
// W[m] = cis(pi*m/128). sign = -1 fwd, +1 inv (unnormalized). Ends in bufA.
__device__ __forceinline__ void fft256(float2* bufA, float2* bufB,
                                       const float2* __restrict__ W,
                                       int j, float sign) {
    float2* x = bufA;
    float2* y = bufB;
#pragma unroll
    for (int st = 0; st < 8; st++) {
        int Ns = 1 << st;
        float2 v0 = x[j];
        float2 v1 = x[j + 128];
        int k = j & (Ns - 1);
        float2 w = W[k << (7 - st)];
        float wy = sign * w.y;
        float2 tv = make_float2(v1.x * w.x - v1.y * wy,
                                v1.x * wy + v1.y * w.x);
        int id = ((j - k) << 1) + k;
        y[id]      = make_float2(v0.x + tv.x, v0.y + tv.y);
        y[id + Ns] = make_float2(v0.x - tv.x, v0.y - tv.y);
        __syncthreads();
        float2* t = x; x = y; y = t;
    }
}

__device__ __forceinline__ void fill_twiddles(float2* W, int tid) {
    if (tid < 128) {
        float s, c;
        sincospif((float)tid * (1.0f / 128.0f), &s, &c);
        W[tid] = make_float2(c, s);
    }
}

__device__ __forceinline__ float freq_coord(int k) {
    return (k < 128) ? (k + 0.5f) * (1.0f / 128.0f)
                     : (k - 255.5f) * (1.0f / 128.0f);
}

// i0e(x) = exp(-x)*I0(x)
__device__ float i0e_dev(float x) {
    if (x > 8.0f) {
        float invx = 1.0f / x;
        float term = 1.0f, sum = 1.0f;
#pragma unroll
        for (int k = 1; k <= 6; k++) {
            float tk = (float)(2 * k - 1);
            term *= tk * tk * invx * (1.0f / (8.0f * (float)k));
            sum  += term;
        }
        return sum * rsqrtf(2.0f * PI_F * x);
    } else {
        float q = 0.25f * x * x;
        float term = 1.0f, sum = 1.0f;
#pragma unroll
        for (int k = 1; k <= 22; k++) {
            float ik = 1.0f / (float)k;
            term *= q * ik * ik;
            sum  += term;
        }
        return sum * __expf(-x);
    }
}

// ---------------- backprojection (unchanged from R9 — at REDG floor) ----------------
__global__ void k_bp(const float* __restrict__ proj, const float* __restrict__ tof,
                     const float* __restrict__ x1l, const float* __restrict__ y1l,
                     const float* __restrict__ x1r, const float* __restrict__ y1r,
                     const float* __restrict__ x2l, const float* __restrict__ y2l,
                     const float* __restrict__ x2r, const float* __restrict__ y2r,
                     int n) {
    int e = blockIdx.x * blockDim.x + threadIdx.x;
    if (e >= n) return;

    float x1 = 0.5f * (x1l[e] + x1r[e]);
    float y1 = 0.5f * (y1l[e] + y1r[e]);
    float x2 = 0.5f * (x2l[e] + x2r[e]);
    float y2 = 0.5f * (y2l[e] + y2r[e]);
    float ddx = x2 - x1, ddy = y2 - y1;
    float L = sqrtf(ddx * ddx + ddy * ddy);

    float step     = L * (1.0f / (float)PNS);
    float inv_step = (float)PNS / L;
    float center   = 0.5f * L + 0.15f * tof[e];

    float lo = (center - WIN_NSIG * SIGMA_MM) * inv_step - 0.5f;
    float hi = (center + WIN_NSIG * SIGMA_MM) * inv_step - 0.5f;
    int i0 = max(0,   (int)ceilf(lo));
    int i1 = min(127, (int)floorf(hi));
    if (i0 > i1) return;

    // incremental Gaussian weight
    float dz = step * INV_SIGMA;
    float z0 = (((float)i0 + 0.5f) * step - center) * INV_SIGMA;
    float w  = proj[e] * step * __expf(-0.5f * z0 * z0);
    float r  = __expf(-dz * (z0 + 0.5f * dz));
    float c  = __expf(-dz * dz);

    float* img = g_img[e & (NREP - 1)];   // de-contend hot pixels 32-way

    float t0f = ((float)i0 + 0.5f) * (1.0f / (float)PNS);
    uint64_t t2   = pack2(t0f, t0f);
    uint64_t dt2  = pack2(1.0f / (float)PNS, 1.0f / (float)PNS);
    uint64_t dd2  = pack2(ddx, ddy);
    uint64_t xy2  = pack2(x1, y1);
    uint64_t h2   = pack2(0.5f, 0.5f);
    uint64_t b2   = pack2(128.0f, 128.0f);

#pragma unroll 8
    for (int i = i0; i <= i1; i++) {
        uint64_t pxy = fma2(t2, dd2, xy2);
        uint64_t gxy = fma2(pxy, h2, b2);
        float gx, gy;
        unpack2(gxy, gx, gy);
        int ix = __float2int_rd(gx);
        int iy = __float2int_rd(gy);
        if ((unsigned)(ix | iy) < 256u)
            atomicAdd(&img[iy * PNX + ix], w);
        w *= r;  r *= c;
        t2 = add2(t2, dt2);
    }
}

// ---------------- fused 2D FFT + filter (persistent, grid barrier) ----------------
// 128 blocks x 256 threads; 2 line-groups of 128 threads: g = tid>>7, j = tid&127.
// All strided accesses are STORES (transpose-on-store); all loads coalesced.
__global__ void k_fft_all(float* __restrict__ out) {
    __shared__ float2 A[2][256];
    __shared__ float2 B[2][256];
    __shared__ float2 W[128];
    int g = threadIdx.x >> 7;
    int j = threadIdx.x & 127;
    int line = blockIdx.x * 2 + g;
    fill_twiddles(W, threadIdx.x);

    // ---- Phase A: row forward FFT (sum 32 replicas via float2, re-zero),
    //      store spectrum TRANSPOSED: g_freqT[k*256 + row] ----
    {
        int row = line;
        float2* base = (float2*)&g_img[0][row * PNX] + j;   // 128 float2 per row
        const int stride2 = (PNX * PNX) / 2;                // float2 stride between reps
        float2 acc = make_float2(0.f, 0.f);
#pragma unroll 8
        for (int rep = 0; rep < NREP; rep++) {
            float2 v = base[rep * stride2];
            acc.x += v.x; acc.y += v.y;
            base[rep * stride2] = make_float2(0.f, 0.f);
        }
        A[g][2 * j]     = make_float2(acc.x, 0.0f);
        A[g][2 * j + 1] = make_float2(acc.y, 0.0f);
        __syncthreads();
        fft256(A[g], B[g], W, j, -1.0f);
        g_freqT[j * PNX + row]         = A[g][j];           // scattered store
        g_freqT[(j + 128) * PNX + row] = A[g][j + 128];
    }

    grid_barrier(FFT_BLOCKS);

    // ---- Phase B: column fwd FFT -> filter -> column inv FFT
    //      load coalesced from g_freqT, store scattered to g_freq[r*256+c] ----
    {
        int c = line;
        A[g][j]       = __ldcg(&g_freqT[c * PNX + j]);      // coalesced load
        A[g][j + 128] = __ldcg(&g_freqT[c * PNX + j + 128]);
        __syncthreads();
        fft256(A[g], B[g], W, j, -1.0f);

        float fc  = freq_coord(c);
        float fc2 = fc * fc;
#pragma unroll
        for (int kk = j; kk < 256; kk += 128) {
            float fr = freq_coord(kk);
            float w0 = fmaf(fr, fr, fc2);
            float gn = FILT_SCALE / i0e_dev(w0 * FILT_C2);
            A[g][kk].x *= gn;
            A[g][kk].y *= gn;
        }
        __syncthreads();
        fft256(A[g], B[g], W, j, +1.0f);
        g_freq[j * PNX + c]         = A[g][j];              // scattered store
        g_freq[(j + 128) * PNX + c] = A[g][j + 128];
    }

    grid_barrier(FFT_BLOCKS);

    // ---- Phase C: row inverse FFT -> real output (coalesced load/store) ----
    {
        int row = line;
        A[g][j]       = __ldcg(&g_freq[row * PNX + j]);     // coalesced load
        A[g][j + 128] = __ldcg(&g_freq[row * PNX + j + 128]);
        __syncthreads();
        fft256(A[g], B[g], W, j, +1.0f);
        out[row * PNX + j]       = A[g][j].x;
        out[row * PNX + j + 128] = A[g][j + 128].x;
    }
}

// ---------------- launch ----------------
extern "C" void kernel_launch(void* const* d_in, const int* in_sizes, int n_in,
                              void* d_out, int out_size) {
    const float* proj = (const float*)d_in[0];
    const float* tof  = (const float*)d_in[1];
    const float* x1l  = (const float*)d_in[2];
    const float* y1l  = (const float*)d_in[3];
    const float* x1r  = (const float*)d_in[4];
    const float* y1r  = (const float*)d_in[5];
    const float* x2l  = (const float*)d_in[6];
    const float* y2l  = (const float*)d_in[7];
    const float* x2r  = (const float*)d_in[8];
    const float* y2r  = (const float*)d_in[9];
    int n = in_sizes[0];

    k_bp<<<(n + 255) / 256, 256>>>(proj, tof, x1l, y1l, x1r, y1r,
                                   x2l, y2l, x2r, y2r, n);
    k_fft_all<<<FFT_BLOCKS, 256>>>((float*)d_out);
}

// round 11
// speedup vs baseline: 2.5461x; 1.0193x over previous
#include <cuda_runtime.h>
#include <cstdint>

// ---------------- static config ----------------
#define PNX 256
#define PNS 128
#define PI_F 3.14159265358979323846f

#define SIGMA_MM   19.108280254777070f
#define INV_SIGMA  (1.0f/19.108280254777070f)
#define FILT_C2    900.91346f
#define FILT_SCALE (1.0f/1024.0f)
#define WIN_NSIG   3.5f
#define NREP       32
#define FFT_BLOCKS 128   // 2 lines/block, 128 < 148 SMs -> co-resident

// ---------------- device scratch ----------------
__device__ float  g_img[NREP][PNX * PNX];   // zero-init at load; re-zeroed each call
__device__ float  g_imgsum[PNX * PNX];      // reduced image
__device__ float2 g_freq[PNX * PNX];
__device__ unsigned g_bar_count = 0;
__device__ volatile unsigned g_bar_gen = 0;

// ---------------- packed f32x2 helpers (sm_100a) ----------------
__device__ __forceinline__ uint64_t pack2(float lo, float hi) {
    uint64_t r; asm("mov.b64 %0, {%1, %2};" : "=l"(r) : "f"(lo), "f"(hi)); return r;
}
__device__ __forceinline__ void unpack2(uint64_t v, float& lo, float& hi) {
    asm("mov.b64 {%0, %1}, %2;" : "=f"(lo), "=f"(hi) : "l"(v));
}
__device__ __forceinline__ uint64_t fma2(uint64_t a, uint64_t b, uint64_t c) {
    uint64_t r; asm("fma.rn.f32x2 %0, %1, %2, %3;" : "=l"(r) : "l"(a), "l"(b), "l"(c)); return r;
}
__device__ __forceinline__ uint64_t add2(uint64_t a, uint64_t b) {
    uint64_t r; asm("add.rn.f32x2 %0, %1, %2;" : "=l"(r) : "l"(a), "l"(b)); return r;
}

// ---------------- grid barrier (all blocks co-resident) ----------------
__device__ __forceinline__ void grid_barrier(unsigned nblocks) {
    __syncthreads();
    if (threadIdx.x == 0) {
        unsigned gen = g_bar_gen;
        __threadfence();
        if (atomicAdd(&g_bar_count, 1u) == nblocks - 1u) {
            g_bar_count = 0;
            __threadfence();
            g_bar_gen = gen + 1u;
        } else {
            while (g_bar_gen == gen) { }
            __threadfence();
        }
    }
    __syncthreads();
}

// ---------------- FFT helpers ----------------
// 256-pt radix-2 Stockham FFT, 128 threads per line, shared twiddles W[128]:
// W[m] = cis(pi*m/128). sign = -1 fwd, +1 inv (unnormalized). Ends in bufA.
__device__ __forceinline__ void fft256(float2* bufA, float2* bufB,
                                       const float2* __restrict__ W,
                                       int j, float sign) {
    float2* x = bufA;
    float2* y = bufB;
#pragma unroll
    for (int st = 0; st < 8; st++) {
        int Ns = 1 << st;
        float2 v0 = x[j];
        float2 v1 = x[j + 128];
        int k = j & (Ns - 1);
        float2 w = W[k << (7 - st)];
        float wy = sign * w.y;
        float2 tv = make_float2(v1.x * w.x - v1.y * wy,
                                v1.x * wy + v1.y * w.x);
        int id = ((j - k) << 1) + k;
        y[id]      = make_float2(v0.x + tv.x, v0.y + tv.y);
        y[id + Ns] = make_float2(v0.x - tv.x, v0.y - tv.y);
        __syncthreads();
        float2* t = x; x = y; y = t;
    }
}

__device__ __forceinline__ void fill_twiddles(float2* W, int tid) {
    if (tid < 128) {
        float s, c;
        sincospif((float)tid * (1.0f / 128.0f), &s, &c);
        W[tid] = make_float2(c, s);
    }
}

__device__ __forceinline__ float freq_coord(int k) {
    return (k < 128) ? (k + 0.5f) * (1.0f / 128.0f)
                     : (k - 255.5f) * (1.0f / 128.0f);
}

// i0e(x) = exp(-x)*I0(x)
__device__ float i0e_dev(float x) {
    if (x > 8.0f) {
        float invx = 1.0f / x;
        float term = 1.0f, sum = 1.0f;
#pragma unroll
        for (int k = 1; k <= 6; k++) {
            float tk = (float)(2 * k - 1);
            term *= tk * tk * invx * (1.0f / (8.0f * (float)k));
            sum  += term;
        }
        return sum * rsqrtf(2.0f * PI_F * x);
    } else {
        float q = 0.25f * x * x;
        float term = 1.0f, sum = 1.0f;
#pragma unroll
        for (int k = 1; k <= 22; k++) {
            float ik = 1.0f / (float)k;
            term *= q * ik * ik;
            sum  += term;
        }
        return sum * __expf(-x);
    }
}

// ---------------- backprojection (at REDG floor) ----------------
__global__ void k_bp(const float* __restrict__ proj, const float* __restrict__ tof,
                     const float* __restrict__ x1l, const float* __restrict__ y1l,
                     const float* __restrict__ x1r, const float* __restrict__ y1r,
                     const float* __restrict__ x2l, const float* __restrict__ y2l,
                     const float* __restrict__ x2r, const float* __restrict__ y2r,
                     int n) {
    int e = blockIdx.x * blockDim.x + threadIdx.x;
    if (e >= n) return;

    float x1 = 0.5f * (x1l[e] + x1r[e]);
    float y1 = 0.5f * (y1l[e] + y1r[e]);
    float x2 = 0.5f * (x2l[e] + x2r[e]);
    float y2 = 0.5f * (y2l[e] + y2r[e]);
    float ddx = x2 - x1, ddy = y2 - y1;
    float L = sqrtf(ddx * ddx + ddy * ddy);

    float step     = L * (1.0f / (float)PNS);
    float inv_step = (float)PNS / L;
    float center   = 0.5f * L + 0.15f * tof[e];

    float lo = (center - WIN_NSIG * SIGMA_MM) * inv_step - 0.5f;
    float hi = (center + WIN_NSIG * SIGMA_MM) * inv_step - 0.5f;
    int i0 = max(0,   (int)ceilf(lo));
    int i1 = min(127, (int)floorf(hi));
    if (i0 > i1) return;

    // incremental Gaussian weight
    float dz = step * INV_SIGMA;
    float z0 = (((float)i0 + 0.5f) * step - center) * INV_SIGMA;
    float w  = proj[e] * step * __expf(-0.5f * z0 * z0);
    float r  = __expf(-dz * (z0 + 0.5f * dz));
    float c  = __expf(-dz * dz);

    float* img = g_img[e & (NREP - 1)];   // de-contend hot pixels 32-way

    float t0f = ((float)i0 + 0.5f) * (1.0f / (float)PNS);
    uint64_t t2   = pack2(t0f, t0f);
    uint64_t dt2  = pack2(1.0f / (float)PNS, 1.0f / (float)PNS);
    uint64_t dd2  = pack2(ddx, ddy);
    uint64_t xy2  = pack2(x1, y1);
    uint64_t h2   = pack2(0.5f, 0.5f);
    uint64_t b2   = pack2(128.0f, 128.0f);

#pragma unroll 8
    for (int i = i0; i <= i1; i++) {
        uint64_t pxy = fma2(t2, dd2, xy2);
        uint64_t gxy = fma2(pxy, h2, b2);
        float gx, gy;
        unpack2(gxy, gx, gy);
        int ix = __float2int_rd(gx);
        int iy = __float2int_rd(gy);
        if ((unsigned)(ix | iy) < 256u)
            atomicAdd(&img[iy * PNX + ix], w);
        w *= r;  r *= c;
        t2 = add2(t2, dt2);
    }
}

// ---------------- replica reduction (full-chip, coalesced) ----------------
// 256 blocks x 256 threads: one thread per pixel. Sum 32 replicas, zero them.
__global__ void k_reduce() {
    int p = blockIdx.x * blockDim.x + threadIdx.x;   // pixel index [0, 65536)
    float acc = 0.0f;
#pragma unroll
    for (int rep = 0; rep < NREP; rep++) {
        acc += g_img[rep][p];
        g_img[rep][p] = 0.0f;
    }
    g_imgsum[p] = acc;
}

// ---------------- fused 2D FFT + filter (persistent, grid barrier) ----------------
// R7 configuration: 128 blocks x 256 threads, 2 line-groups of 128 threads.
__global__ void k_fft_all(float* __restrict__ out) {
    __shared__ float2 A[2][256];
    __shared__ float2 B[2][256];
    __shared__ float2 W[128];
    int g = threadIdx.x >> 7;
    int j = threadIdx.x & 127;
    int line = blockIdx.x * 2 + g;
    fill_twiddles(W, threadIdx.x);

    // ---- Phase A: row forward FFT (coalesced read of reduced image) ----
    {
        int row = line;
        A[g][j]       = make_float2(g_imgsum[row * PNX + j],       0.0f);
        A[g][j + 128] = make_float2(g_imgsum[row * PNX + j + 128], 0.0f);
        __syncthreads();
        fft256(A[g], B[g], W, j, -1.0f);
        g_freq[row * PNX + j]       = A[g][j];
        g_freq[row * PNX + j + 128] = A[g][j + 128];
    }

    grid_barrier(FFT_BLOCKS);

    // ---- Phase B: column fwd FFT -> filter -> column inv FFT ----
    {
        int c = line;
        A[g][j]       = __ldcg(&g_freq[j * PNX + c]);
        A[g][j + 128] = __ldcg(&g_freq[(j + 128) * PNX + c]);
        __syncthreads();
        fft256(A[g], B[g], W, j, -1.0f);

        float fc  = freq_coord(c);
        float fc2 = fc * fc;
#pragma unroll
        for (int kk = j; kk < 256; kk += 128) {
            float fr = freq_coord(kk);
            float w0 = fmaf(fr, fr, fc2);
            float gn = FILT_SCALE / i0e_dev(w0 * FILT_C2);
            A[g][kk].x *= gn;
            A[g][kk].y *= gn;
        }
        __syncthreads();
        fft256(A[g], B[g], W, j, +1.0f);
        g_freq[j * PNX + c]         = A[g][j];
        g_freq[(j + 128) * PNX + c] = A[g][j + 128];
    }

    grid_barrier(FFT_BLOCKS);

    // ---- Phase C: row inverse FFT -> real output ----
    {
        int row = line;
        A[g][j]       = __ldcg(&g_freq[row * PNX + j]);
        A[g][j + 128] = __ldcg(&g_freq[row * PNX + j + 128]);
        __syncthreads();
        fft256(A[g], B[g], W, j, +1.0f);
        out[row * PNX + j]       = A[g][j].x;
        out[row * PNX + j + 128] = A[g][j + 128].x;
    }
}

// ---------------- launch ----------------
extern "C" void kernel_launch(void* const* d_in, const int* in_sizes, int n_in,
                              void* d_out, int out_size) {
    const float* proj = (const float*)d_in[0];
    const float* tof  = (const float*)d_in[1];
    const float* x1l  = (const float*)d_in[2];
    const float* y1l  = (const float*)d_in[3];
    const float* x1r  = (const float*)d_in[4];
    const float* y1r  = (const float*)d_in[5];
    const float* x2l  = (const float*)d_in[6];
    const float* y2l  = (const float*)d_in[7];
    const float* x2r  = (const float*)d_in[8];
    const float* y2r  = (const float*)d_in[9];
    int n = in_sizes[0];

    k_bp<<<(n + 255) / 256, 256>>>(proj, tof, x1l, y1l, x1r, y1r,
                                   x2l, y2l, x2r, y2r, n);
    k_reduce<<<(PNX * PNX) / 256, 256>>>();
    k_fft_all<<<FFT_BLOCKS, 256>>>((float*)d_out);
}